// round 3
// baseline (speedup 1.0000x reference)
#include <cuda_runtime.h>
#include <math.h>

// Problem constants
#define BATCH 256
#define EDIM 128
#define HDIM 128
#define NTOK 511     // tokens per batch (2^9 - 1)
#define NARITY 255   // internal nodes per batch (2^8 - 1)

// Tiling
#define TM 32        // rows (nodes) per block
#define TJ 32        // output columns per block
#define TK 16        // K-chunk staged in shared

// Ping-pong scratch for h and c: max 256 nodes/batch at leaf level.
// 2 * 2 * 256*256*128 floats = 134 MB static device memory (allowed).
__device__ float g_h[2][BATCH * 256 * HDIM];
__device__ float g_c[2][BATCH * 256 * HDIM];

__device__ __forceinline__ float sigmoid_(float x) {
    return 1.0f / (1.0f + expf(-x));
}
__device__ __forceinline__ float tanh_(float x) {
    // 1 - 2/(e^{2x}+1): accurate and safe under fast-math (uses expf only)
    return 1.0f - 2.0f / (expf(2.0f * x) + 1.0f);
}

// ---------------------------------------------------------------------------
// Leaf kernel: h = tanh(emb[tok] @ W[3] + bW[3]), c = 0
// rows = BATCH*256, grid.x = rows/TM, grid.y = HDIM/TJ
// ---------------------------------------------------------------------------
__global__ __launch_bounds__(256, 2)
void leaf_kernel(const int* __restrict__ tokens,
                 const float* __restrict__ emb,
                 const float* __restrict__ W,
                 const float* __restrict__ bW)
{
    __shared__ __align__(16) float sh_x[TM][EDIM];
    __shared__ __align__(16) float sh_w[TK][TJ];

    float* __restrict__ h_out = g_h[0];
    float* __restrict__ c_out = g_c[0];

    const int tid  = threadIdx.x;
    const int lane = tid & 31;
    const int rg   = tid >> 5;          // 0..7 (warp id = row group)
    const int colb = blockIdx.y * TJ;
    const int col  = colb + lane;
    const int row0 = blockIdx.x * TM;

    // Stage x rows (warp rg loads its 4 rows, float4-coalesced)
#pragma unroll
    for (int i = 0; i < 4; i++) {
        const int r   = rg * 4 + i;
        const int row = row0 + r;
        const int b   = row >> 8;
        const int j   = row & 255;
        const int tok = __ldg(&tokens[b * NTOK + 255 + j]);
        *(float4*)&sh_x[r][lane * 4] =
            *(const float4*)(emb + (size_t)tok * EDIM + lane * 4);
    }

    float acc[4] = {0.f, 0.f, 0.f, 0.f};
    const float* __restrict__ W3 = W + 3 * EDIM * HDIM;

    for (int kc = 0; kc < EDIM / TK; kc++) {
        __syncthreads();
#pragma unroll
        for (int j = 0; j < 2; j++) {      // 16*32 = 512 elems, 2/thread
            const int idx = j * 256 + tid;
            const int kk  = idx >> 5;
            const int c   = idx & 31;
            sh_w[kk][c] = __ldg(&W3[(kc * TK + kk) * HDIM + colb + c]);
        }
        __syncthreads();
#pragma unroll
        for (int kk = 0; kk < TK; kk += 4) {
            const int k = kc * TK + kk;
#pragma unroll
            for (int i = 0; i < 4; i++) {
                const float4 xv = *(const float4*)&sh_x[rg * 4 + i][k];
                acc[i] += xv.x * sh_w[kk + 0][lane];
                acc[i] += xv.y * sh_w[kk + 1][lane];
                acc[i] += xv.z * sh_w[kk + 2][lane];
                acc[i] += xv.w * sh_w[kk + 3][lane];
            }
        }
    }

    const float bias = __ldg(&bW[3 * HDIM + col]);
#pragma unroll
    for (int i = 0; i < 4; i++) {
        const int row = row0 + rg * 4 + i;
        h_out[(size_t)row * HDIM + col] = tanh_(acc[i] + bias);
        c_out[(size_t)row * HDIM + col] = 0.0f;
    }
}

// ---------------------------------------------------------------------------
// Internal-level kernel: fused Wx/Ubin/Uun GEMMs + LSTM pointwise.
// Level l: cnt = 2^l nodes/batch. rows = BATCH*cnt (row = b*cnt + n).
// Children live at rows b*2*cnt + 2n (+1) of the input buffers.
// ---------------------------------------------------------------------------
__global__ __launch_bounds__(256, 2)
void level_kernel(const int* __restrict__ tokens,
                  const int* __restrict__ arity,
                  const float* __restrict__ emb,
                  const float* __restrict__ W,    const float* __restrict__ bW,
                  const float* __restrict__ Ubin, const float* __restrict__ bUbin,
                  const float* __restrict__ Uun,  const float* __restrict__ bUun,
                  int pin, int pout, int lcnt)
{
    __shared__ __align__(16) float sh_hl[TM][HDIM];
    __shared__ __align__(16) float sh_b [TM][HDIM];   // x (phase A), then h_r (phase B)
    __shared__ __align__(16) float sh_w [5][TK][TJ];

    const float* __restrict__ h_in  = g_h[pin];
    const float* __restrict__ c_in  = g_c[pin];
    float* __restrict__ h_out = g_h[pout];
    float* __restrict__ c_out = g_c[pout];

    const int tid  = threadIdx.x;
    const int lane = tid & 31;
    const int rg   = tid >> 5;
    const int cnt  = 1 << lcnt;
    const int o2   = cnt - 1;
    const int colb = blockIdx.y * TJ;
    const int col  = colb + lane;
    const int row0 = blockIdx.x * TM;

    // Stage x (into sh_b) and h_l
#pragma unroll
    for (int i = 0; i < 4; i++) {
        const int r   = rg * 4 + i;
        const int row = row0 + r;
        const int b   = row >> lcnt;
        const int n   = row & (cnt - 1);
        const int tok = __ldg(&tokens[b * NTOK + o2 + n]);
        *(float4*)&sh_b[r][lane * 4] =
            *(const float4*)(emb + (size_t)tok * EDIM + lane * 4);
        const int childrow = (b << (lcnt + 1)) + 2 * n;
        *(float4*)&sh_hl[r][lane * 4] =
            *(const float4*)(h_in + (size_t)childrow * HDIM + lane * 4);
    }

    float awx[4][4];
    float aub[5][4];
    float auu[4][4];
#pragma unroll
    for (int g = 0; g < 4; g++)
#pragma unroll
        for (int i = 0; i < 4; i++) { awx[g][i] = 0.f; auu[g][i] = 0.f; }
#pragma unroll
    for (int g = 0; g < 5; g++)
#pragma unroll
        for (int i = 0; i < 4; i++) aub[g][i] = 0.f;

    // ---- Phase A: Wx = x @ W[g] (g=0..3, K=128, x in sh_b) ----
    for (int kc = 0; kc < EDIM / TK; kc++) {
        __syncthreads();
#pragma unroll
        for (int j = 0; j < 8; j++) {      // 4*16*32 = 2048 elems
            const int idx = j * 256 + tid;
            const int g   = idx >> 9;
            const int kk  = (idx >> 5) & 15;
            const int c   = idx & 31;
            sh_w[g][kk][c] = __ldg(&W[((g << 7) + kc * TK + kk) * HDIM + colb + c]);
        }
        __syncthreads();
#pragma unroll
        for (int kk = 0; kk < TK; kk += 4) {
            const int k = kc * TK + kk;
#pragma unroll
            for (int i = 0; i < 4; i++) {
                const float4 xv = *(const float4*)&sh_b[rg * 4 + i][k];
                const float xs[4] = {xv.x, xv.y, xv.z, xv.w};
#pragma unroll
                for (int q = 0; q < 4; q++)
#pragma unroll
                    for (int g = 0; g < 4; g++)
                        awx[g][i] += xs[q] * sh_w[g][kk + q][lane];
            }
        }
    }

    // Restage: h_r into sh_b
    __syncthreads();
#pragma unroll
    for (int i = 0; i < 4; i++) {
        const int r   = rg * 4 + i;
        const int row = row0 + r;
        const int b   = row >> lcnt;
        const int n   = row & (cnt - 1);
        const int childrow = (b << (lcnt + 1)) + 2 * n + 1;
        *(float4*)&sh_b[r][lane * 4] =
            *(const float4*)(h_in + (size_t)childrow * HDIM + lane * 4);
    }

    // ---- Phase B: Ub = [h_l, h_r] @ Ubin[g] (g=0..4, K=256) ----
    for (int half = 0; half < 2; half++) {
        const float (*src)[HDIM] = half ? (const float(*)[HDIM])sh_b
                                        : (const float(*)[HDIM])sh_hl;
        for (int kc = 0; kc < EDIM / TK; kc++) {
            __syncthreads();
#pragma unroll
            for (int j = 0; j < 10; j++) {  // 5*16*32 = 2560 elems
                const int idx = j * 256 + tid;
                const int g   = idx / 512;
                const int kk  = (idx >> 5) & 15;
                const int c   = idx & 31;
                sh_w[g][kk][c] =
                    __ldg(&Ubin[(g * 256 + half * 128 + kc * TK + kk) * HDIM + colb + c]);
            }
            __syncthreads();
#pragma unroll
            for (int kk = 0; kk < TK; kk += 4) {
                const int k = kc * TK + kk;
#pragma unroll
                for (int i = 0; i < 4; i++) {
                    const float4 xv = *(const float4*)&src[rg * 4 + i][k];
                    const float xs[4] = {xv.x, xv.y, xv.z, xv.w};
#pragma unroll
                    for (int q = 0; q < 4; q++)
#pragma unroll
                        for (int g = 0; g < 5; g++)
                            aub[g][i] += xs[q] * sh_w[g][kk + q][lane];
                }
            }
        }
    }

    // ---- Phase C: Uu = h_l @ Uun[g] (g=0..3, K=128) ----
    for (int kc = 0; kc < EDIM / TK; kc++) {
        __syncthreads();
#pragma unroll
        for (int j = 0; j < 8; j++) {
            const int idx = j * 256 + tid;
            const int g   = idx >> 9;
            const int kk  = (idx >> 5) & 15;
            const int c   = idx & 31;
            sh_w[g][kk][c] = __ldg(&Uun[((g << 7) + kc * TK + kk) * HDIM + colb + c]);
        }
        __syncthreads();
#pragma unroll
        for (int kk = 0; kk < TK; kk += 4) {
            const int k = kc * TK + kk;
#pragma unroll
            for (int i = 0; i < 4; i++) {
                const float4 xv = *(const float4*)&sh_hl[rg * 4 + i][k];
                const float xs[4] = {xv.x, xv.y, xv.z, xv.w};
#pragma unroll
                for (int q = 0; q < 4; q++)
#pragma unroll
                    for (int g = 0; g < 4; g++)
                        auu[g][i] += xs[q] * sh_w[g][kk + q][lane];
            }
        }
    }

    // ---- Epilogue: biases + gate nonlinearities + cell update ----
    float bwx[4], bub[5], buu[4];
#pragma unroll
    for (int g = 0; g < 4; g++) {
        bwx[g] = __ldg(&bW[g * HDIM + col]);
        buu[g] = __ldg(&bUun[g * HDIM + col]);
    }
#pragma unroll
    for (int g = 0; g < 5; g++) bub[g] = __ldg(&bUbin[g * HDIM + col]);

#pragma unroll
    for (int i = 0; i < 4; i++) {
        const int row = row0 + rg * 4 + i;
        const int b   = row >> lcnt;
        const int n   = row & (cnt - 1);
        const int ar  = __ldg(&arity[b * NARITY + o2 + n]);
        const int childrow = (b << (lcnt + 1)) + 2 * n;
        const float cl = __ldg(&c_in[(size_t)childrow * HDIM + col]);

        const float wx0 = awx[0][i] + bwx[0];
        const float wx1 = awx[1][i] + bwx[1];
        const float wx2 = awx[2][i] + bwx[2];
        const float wx3 = awx[3][i] + bwx[3];

        float hv, cv;
        if (ar == 1) {  // binary node
            const float cr = __ldg(&c_in[(size_t)(childrow + 1) * HDIM + col]);
            const float ig = sigmoid_(wx0 + aub[0][i] + bub[0]);
            const float fl = sigmoid_(wx1 + aub[1][i] + bub[1]);
            const float fr = sigmoid_(wx1 + aub[2][i] + bub[2]);
            const float og = sigmoid_(wx2 + aub[3][i] + bub[3]);
            const float ug = tanh_   (wx3 + aub[4][i] + bub[4]);
            cv = ig * ug + fl * cl + fr * cr;
            hv = og * tanh_(cv);
        } else {        // unary node (left child only)
            const float ig = sigmoid_(wx0 + auu[0][i] + buu[0]);
            const float fg = sigmoid_(wx1 + auu[1][i] + buu[1]);
            const float og = sigmoid_(wx2 + auu[2][i] + buu[2]);
            const float ug = tanh_   (wx3 + auu[3][i] + buu[3]);
            cv = ig * ug + fg * cl;
            hv = og * tanh_(cv);
        }
        h_out[(size_t)row * HDIM + col] = hv;
        c_out[(size_t)row * HDIM + col] = cv;
    }
}

// ---------------------------------------------------------------------------
// Final copy: out[0:32768] = h_root (B,H), out[32768:65536] = c_root (B,H)
// ---------------------------------------------------------------------------
__global__ void copy_out_kernel(int pin, float* __restrict__ out)
{
    const int t = blockIdx.x * blockDim.x + threadIdx.x;  // 0..32767
    out[t]                      = g_h[pin][t];
    out[BATCH * HDIM + t]       = g_c[pin][t];
}

// ---------------------------------------------------------------------------
extern "C" void kernel_launch(void* const* d_in, const int* in_sizes, int n_in,
                              void* d_out, int out_size)
{
    const int*   tokens = (const int*)  d_in[0];
    const int*   arity  = (const int*)  d_in[1];
    const float* emb    = (const float*)d_in[2];
    const float* W      = (const float*)d_in[3];
    const float* bW     = (const float*)d_in[4];
    const float* Ubin   = (const float*)d_in[5];
    const float* bUbin  = (const float*)d_in[6];
    const float* Uun    = (const float*)d_in[7];
    const float* bUun   = (const float*)d_in[8];
    float* out = (float*)d_out;

    // Leaves: 65536 rows -> grid (2048, 4), writes buffers [0]
    {
        dim3 grid(BATCH * 256 / TM, HDIM / TJ);
        leaf_kernel<<<grid, 256>>>(tokens, emb, W, bW);
    }

    // Levels 7..0
    int pin = 0;
    for (int l = 7; l >= 0; l--) {
        const int pout = 1 - pin;
        dim3 grid((BATCH << l) / TM, HDIM / TJ);
        level_kernel<<<grid, 256>>>(tokens, arity, emb,
                                    W, bW, Ubin, bUbin, Uun, bUun,
                                    pin, pout, l);
        pin = pout;
    }

    // Root outputs
    copy_out_kernel<<<(BATCH * HDIM) / 256, 256>>>(pin, out);
}

// round 5
// speedup vs baseline: 1.7416x; 1.7416x over previous
#include <cuda_runtime.h>
#include <cuda_bf16.h>
#include <cstdint>
#include <math.h>

#define BATCH 256
#define HDIM  128
#define NTOK  511
#define NARITY 255

// ---------------------------------------------------------------------------
// Static device scratch (allocation-free rule):
//   Bc   : combined transposed weights [13 gates][n=128][k=256] bf16 hi/lo
//   Aleaf: leaf embeddings [65536][128] bf16 hi/lo
//   Az   : per-level inputs [2 ping-pong][32768 rows][384 k] bf16 hi/lo
//          (k layout: x 0..127, h_l 128..255, h_r 256..383)
//   gbuf : gate pre-activations [32768][13*128] fp32
//   cbuf : cell-state ping-pong [2][65536][128] fp32
// ---------------------------------------------------------------------------
__device__ __nv_bfloat16 g_Bc_hi[13 * 128 * 256];
__device__ __nv_bfloat16 g_Bc_lo[13 * 128 * 256];
__device__ __nv_bfloat16 g_Aleaf_hi[65536 * 128];
__device__ __nv_bfloat16 g_Aleaf_lo[65536 * 128];
__device__ __nv_bfloat16 g_Az_hi[2][32768 * 384];
__device__ __nv_bfloat16 g_Az_lo[2][32768 * 384];
__device__ float         g_gbuf[32768 * 1664];
__device__ float         g_cbuf[2][65536 * 128];

__device__ __forceinline__ float sigmoid_(float x) { return 1.0f / (1.0f + expf(-x)); }
__device__ __forceinline__ float tanh_(float x)    { return 1.0f - 2.0f / (expf(2.0f * x) + 1.0f); }

__device__ __forceinline__ void split_bf16(float v, __nv_bfloat16& hi, __nv_bfloat16& lo) {
    hi = __float2bfloat16(v);
    lo = __float2bfloat16(v - __bfloat162float(hi));
}

// ---------------------------------------------------------------------------
// prep_B: combined transposed weights B[g][n][k] (k contiguous), bf16 hi/lo.
//   g 0..3 : W[g]      (k<128 valid, rest 0)
//   g 4..8 : Ubin[g-4] (k<256)
//   g 9..12: Uun[g-9]  (k<128 valid, rest 0)
// ---------------------------------------------------------------------------
__global__ void prep_B_kernel(const float* __restrict__ W,
                              const float* __restrict__ Ubin,
                              const float* __restrict__ Uun)
{
    const int idx = blockIdx.x * 256 + threadIdx.x;
    if (idx >= 13 * 128 * 256) return;
    const int g = idx >> 15;
    const int n = (idx >> 8) & 127;
    const int k = idx & 255;
    float v;
    if (g < 4)       v = (k < 128) ? W[g * 16384 + k * 128 + n] : 0.f;
    else if (g < 9)  v = Ubin[(g - 4) * 32768 + k * 128 + n];
    else             v = (k < 128) ? Uun[(g - 9) * 16384 + k * 128 + n] : 0.f;
    split_bf16(v, g_Bc_hi[idx], g_Bc_lo[idx]);
}

// stage leaf A = emb[tokens[:,255:]]
__global__ void stage_leaf_kernel(const int* __restrict__ tokens,
                                  const float* __restrict__ emb)
{
    const int idx = blockIdx.x * 256 + threadIdx.x;   // 0 .. 65536*128-1
    const int row = idx >> 7;
    const int col = idx & 127;
    const int b = row >> 8, n = row & 255;
    const int tok = __ldg(&tokens[b * NTOK + 255 + n]);
    const float v = __ldg(&emb[(size_t)tok * 128 + col]);
    split_bf16(v, g_Aleaf_hi[idx], g_Aleaf_lo[idx]);
}

// stage x part of Az for level l
__global__ void stage_x_kernel(const int* __restrict__ tokens,
                               const float* __restrict__ emb, int l)
{
    const int idx = blockIdx.x * 256 + threadIdx.x;
    const int row = idx >> 7;
    const int col = idx & 127;
    const int b = row >> l;
    const int n = row - (b << l);
    const int tok = __ldg(&tokens[b * NTOK + ((1 << l) - 1) + n]);
    const float v = __ldg(&emb[(size_t)tok * 128 + col]);
    __nv_bfloat16 hi, lo;
    split_bf16(v, hi, lo);
    const size_t o = (size_t)row * 384 + col;
    g_Az_hi[l & 1][o] = hi;
    g_Az_lo[l & 1][o] = lo;
}

// ---------------------------------------------------------------------------
// GEMM kernel via mma.sync m16n8k16 bf16 (3-term split for ~fp32 accuracy).
// Block: 128 rows x 1 gate (N=128). 8 warps, 2(M) x 4(N), warp tile 64x32.
// mode 0: write raw gate pre-activations to gbuf.
// mode 1 (leaf): tanh+bias epilogue, scatter h (bf16 split) to level-7 Az
//                h-slots and c=0 to cbuf[0].
// ---------------------------------------------------------------------------
__global__ __launch_bounds__(256, 2)
void gemm_kernel(int mode, int azi, const float* __restrict__ bW)
{
    __shared__ __align__(16) __nv_bfloat16 sA[128][72];
    __shared__ __align__(16) __nv_bfloat16 sB[128][72];

    const int tid  = threadIdx.x;
    const int wid  = tid >> 5;
    const int lane = tid & 31;
    const int grp  = lane >> 2;      // 0..7
    const int tig  = lane & 3;       // 0..3
    const int wm   = wid & 1;        // warp M index (0..1)
    const int wn   = wid >> 1;       // warp N index (0..3)
    const int g    = (mode == 1) ? 3 : (int)blockIdx.y;
    const int row0 = blockIdx.x * 128;

    const __nv_bfloat16* Ah = (mode == 1) ? g_Aleaf_hi : g_Az_hi[azi];
    const __nv_bfloat16* Al = (mode == 1) ? g_Aleaf_lo : g_Az_lo[azi];
    const int astride = (mode == 1) ? 128 : 384;
    int nch, akb;
    if (mode == 1 || g < 4) { nch = 2; akb = 0;   }   // x gates, K=128
    else if (g < 9)         { nch = 4; akb = 128; }   // Ubin,   K=256
    else                    { nch = 2; akb = 128; }   // Uun,    K=128 (h_l)

    float acc[4][4][4];
#pragma unroll
    for (int i = 0; i < 4; i++)
#pragma unroll
        for (int j = 0; j < 4; j++)
#pragma unroll
            for (int q = 0; q < 4; q++) acc[i][j][q] = 0.f;

    const int lrow  = tid >> 1;   // staging row (0..127)
    const int lhalf = tid & 1;    // which 32-element half

    for (int t = 0; t < 3; t++) {
        const __nv_bfloat16* As = (t == 1) ? Al : Ah;
        const __nv_bfloat16* Bs = (t == 2) ? g_Bc_lo : g_Bc_hi;
        for (int c = 0; c < nch; c++) {
            __syncthreads();   // protect previous iteration's reads
            const __nv_bfloat16* ap =
                As + (size_t)(row0 + lrow) * astride + akb + c * 64 + lhalf * 32;
            const __nv_bfloat16* bp =
                Bs + (size_t)g * 32768 + (size_t)lrow * 256 + c * 64 + lhalf * 32;
#pragma unroll
            for (int j = 0; j < 4; j++) {
                *(uint4*)&sA[lrow][lhalf * 32 + j * 8] = *(const uint4*)(ap + j * 8);
                *(uint4*)&sB[lrow][lhalf * 32 + j * 8] = *(const uint4*)(bp + j * 8);
            }
            __syncthreads();

#pragma unroll
            for (int ks = 0; ks < 4; ks++) {
                const int k0 = ks * 16;
                uint32_t a[4][4], b[4][2];
#pragma unroll
                for (int i = 0; i < 4; i++) {
                    const int r = wm * 64 + i * 16 + grp;
                    a[i][0] = *(const uint32_t*)&sA[r    ][k0 + tig * 2];
                    a[i][1] = *(const uint32_t*)&sA[r + 8][k0 + tig * 2];
                    a[i][2] = *(const uint32_t*)&sA[r    ][k0 + 8 + tig * 2];
                    a[i][3] = *(const uint32_t*)&sA[r + 8][k0 + 8 + tig * 2];
                }
#pragma unroll
                for (int j = 0; j < 4; j++) {
                    const int n = wn * 32 + j * 8 + grp;
                    b[j][0] = *(const uint32_t*)&sB[n][k0 + tig * 2];
                    b[j][1] = *(const uint32_t*)&sB[n][k0 + 8 + tig * 2];
                }
#pragma unroll
                for (int i = 0; i < 4; i++)
#pragma unroll
                    for (int j = 0; j < 4; j++)
                        asm volatile(
                            "mma.sync.aligned.m16n8k16.row.col.f32.bf16.bf16.f32 "
                            "{%0,%1,%2,%3}, {%4,%5,%6,%7}, {%8,%9}, {%0,%1,%2,%3};"
                            : "+f"(acc[i][j][0]), "+f"(acc[i][j][1]),
                              "+f"(acc[i][j][2]), "+f"(acc[i][j][3])
                            : "r"(a[i][0]), "r"(a[i][1]), "r"(a[i][2]), "r"(a[i][3]),
                              "r"(b[j][0]), "r"(b[j][1]));
            }
        }
    }

    // ---- Epilogue ----
    if (mode == 0) {
        const int gcb = g * 128 + wn * 32;
#pragma unroll
        for (int i = 0; i < 4; i++) {
            const int r = row0 + wm * 64 + i * 16 + grp;
#pragma unroll
            for (int j = 0; j < 4; j++) {
                const int col = gcb + j * 8 + tig * 2;
                *(float2*)&g_gbuf[(size_t)r * 1664 + col] =
                    make_float2(acc[i][j][0], acc[i][j][1]);
                *(float2*)&g_gbuf[(size_t)(r + 8) * 1664 + col] =
                    make_float2(acc[i][j][2], acc[i][j][3]);
            }
        }
    } else {
        // Leaf: h = tanh(acc + bW[3]); scatter into level-7 Az h-slots; c = 0.
#pragma unroll
        for (int j = 0; j < 4; j++) {
            const int col = wn * 32 + j * 8 + tig * 2;
            const float b0 = __ldg(&bW[384 + col]);
            const float b1 = __ldg(&bW[384 + col + 1]);
#pragma unroll
            for (int i = 0; i < 4; i++) {
#pragma unroll
                for (int half = 0; half < 2; half++) {
                    const int lr = row0 + wm * 64 + i * 16 + grp + half * 8;
                    const float h0 = tanh_(acc[i][j][half * 2 + 0] + b0);
                    const float h1 = tanh_(acc[i][j][half * 2 + 1] + b1);
                    const int bb = lr >> 8, nn = lr & 255;
                    const int prow = (bb << 7) + (nn >> 1);
                    const int side = nn & 1;
                    const size_t o = (size_t)prow * 384 + 128 + side * 128 + col;
                    __nv_bfloat16 hi0, lo0, hi1, lo1;
                    split_bf16(h0, hi0, lo0);
                    split_bf16(h1, hi1, lo1);
                    __nv_bfloat162 vh; vh.x = hi0; vh.y = hi1;
                    __nv_bfloat162 vl; vl.x = lo0; vl.y = lo1;
                    *(__nv_bfloat162*)&g_Az_hi[1][o] = vh;
                    *(__nv_bfloat162*)&g_Az_lo[1][o] = vl;
                    *(float2*)&g_cbuf[0][(size_t)lr * 128 + col] = make_float2(0.f, 0.f);
                }
            }
        }
    }
}

// ---------------------------------------------------------------------------
// Pointwise LSTM cell update for level l; writes c (fp32) and next-level h
// (bf16 split) directly into parent Az slots; at l==0 writes d_out.
// ---------------------------------------------------------------------------
__global__ __launch_bounds__(128)
void pointwise_kernel(int l, int cin,
                      const int* __restrict__ arity,
                      const float* __restrict__ bW,
                      const float* __restrict__ bUbin,
                      const float* __restrict__ bUun,
                      float* __restrict__ out)
{
    const int row = blockIdx.x;
    const int col = threadIdx.x;
    const int b = row >> l;
    const int n = row - (b << l);
    const int ar = __ldg(&arity[b * NARITY + ((1 << l) - 1) + n]);
    const size_t childrow = ((size_t)b << (l + 1)) + 2 * n;
    const float cl = g_cbuf[cin][childrow * 128 + col];
    const float cr = g_cbuf[cin][(childrow + 1) * 128 + col];
    const float* gb = g_gbuf + (size_t)row * 1664;

    const float wx0 = gb[0 * 128 + col] + __ldg(&bW[0 * 128 + col]);
    const float wx1 = gb[1 * 128 + col] + __ldg(&bW[1 * 128 + col]);
    const float wx2 = gb[2 * 128 + col] + __ldg(&bW[2 * 128 + col]);
    const float wx3 = gb[3 * 128 + col] + __ldg(&bW[3 * 128 + col]);

    float hv, cv;
    if (ar == 1) {
        const float ig = sigmoid_(wx0 + gb[4 * 128 + col] + __ldg(&bUbin[0 * 128 + col]));
        const float fl = sigmoid_(wx1 + gb[5 * 128 + col] + __ldg(&bUbin[1 * 128 + col]));
        const float fr = sigmoid_(wx1 + gb[6 * 128 + col] + __ldg(&bUbin[2 * 128 + col]));
        const float og = sigmoid_(wx2 + gb[7 * 128 + col] + __ldg(&bUbin[3 * 128 + col]));
        const float ug = tanh_   (wx3 + gb[8 * 128 + col] + __ldg(&bUbin[4 * 128 + col]));
        cv = ig * ug + fl * cl + fr * cr;
        hv = og * tanh_(cv);
    } else {
        const float ig = sigmoid_(wx0 + gb[ 9 * 128 + col] + __ldg(&bUun[0 * 128 + col]));
        const float fg = sigmoid_(wx1 + gb[10 * 128 + col] + __ldg(&bUun[1 * 128 + col]));
        const float og = sigmoid_(wx2 + gb[11 * 128 + col] + __ldg(&bUun[2 * 128 + col]));
        const float ug = tanh_   (wx3 + gb[12 * 128 + col] + __ldg(&bUun[3 * 128 + col]));
        cv = ig * ug + fg * cl;
        hv = og * tanh_(cv);
    }

    g_cbuf[1 - cin][(size_t)row * 128 + col] = cv;

    if (l == 0) {
        out[row * 128 + col] = hv;
        out[BATCH * HDIM + row * 128 + col] = cv;
    } else {
        const int prow = (b << (l - 1)) + (n >> 1);
        const int side = n & 1;
        __nv_bfloat16 hi, lo;
        split_bf16(hv, hi, lo);
        const size_t o = (size_t)prow * 384 + 128 + side * 128 + col;
        g_Az_hi[(l - 1) & 1][o] = hi;
        g_Az_lo[(l - 1) & 1][o] = lo;
    }
}

// ---------------------------------------------------------------------------
extern "C" void kernel_launch(void* const* d_in, const int* in_sizes, int n_in,
                              void* d_out, int out_size)
{
    const int*   tokens = (const int*)  d_in[0];
    const int*   arity  = (const int*)  d_in[1];
    const float* emb    = (const float*)d_in[2];
    const float* W      = (const float*)d_in[3];
    const float* bW     = (const float*)d_in[4];
    const float* Ubin   = (const float*)d_in[5];
    const float* bUbin  = (const float*)d_in[6];
    const float* Uun    = (const float*)d_in[7];
    const float* bUun   = (const float*)d_in[8];
    float* out = (float*)d_out;

    // Weight prep + leaf staging
    prep_B_kernel<<<(13 * 128 * 256 + 255) / 256, 256>>>(W, Ubin, Uun);
    stage_leaf_kernel<<<(65536 * 128) / 256, 256>>>(tokens, emb);

    // Leaf GEMM (gate 3 = W[3]): h into level-7 Az h-slots, c=0 into cbuf[0]
    {
        dim3 grid(65536 / 128, 1);
        gemm_kernel<<<grid, 256>>>(1, 0, bW);
    }

    // Levels 7..0
    for (int l = 7; l >= 0; l--) {
        const int rows = BATCH << l;
        const int cin = (7 - l) & 1;
        stage_x_kernel<<<(rows * 128) / 256, 256>>>(tokens, emb, l);
        dim3 ggrid(rows / 128, 13);
        gemm_kernel<<<ggrid, 256>>>(0, l & 1, bW);
        pointwise_kernel<<<rows, 128>>>(l, cin, arity, bW, bUbin, bUun,
                                        (l == 0) ? out : nullptr);
    }
}

// round 6
// speedup vs baseline: 1.7635x; 1.0125x over previous
#include <cuda_runtime.h>
#include <cuda_bf16.h>
#include <cuda_fp16.h>
#include <cstdint>
#include <math.h>

#define BATCH 256
#define HDIM  128
#define NTOK  511
#define NARITY 255

// ---------------------------------------------------------------------------
// Static device scratch:
//   Bc   : combined transposed weights [13 gates][n=128][k=256] bf16 hi/lo
//   Aleaf: leaf embeddings [65536][128] bf16 hi/lo
//   Az   : per-level inputs [2 ping-pong][32768 rows][384 k] bf16 hi/lo
//   gbuf : gate pre-activations [32768][13*128] fp16
//   cbuf : cell-state ping-pong [2][65536][128] fp32
// ---------------------------------------------------------------------------
__device__ __align__(16) __nv_bfloat16 g_Bc_hi[13 * 128 * 256];
__device__ __align__(16) __nv_bfloat16 g_Bc_lo[13 * 128 * 256];
__device__ __align__(16) __nv_bfloat16 g_Aleaf_hi[65536 * 128];
__device__ __align__(16) __nv_bfloat16 g_Aleaf_lo[65536 * 128];
__device__ __align__(16) __nv_bfloat16 g_Az_hi[2][32768 * 384];
__device__ __align__(16) __nv_bfloat16 g_Az_lo[2][32768 * 384];
__device__ __align__(16) __half        g_gbuf[32768 * 1664];
__device__ __align__(16) float         g_cbuf[2][65536 * 128];

__device__ __forceinline__ float sigmoid_(float x) { return 1.0f / (1.0f + expf(-x)); }
__device__ __forceinline__ float tanh_(float x)    { return 1.0f - 2.0f / (expf(2.0f * x) + 1.0f); }

__device__ __forceinline__ void split_bf16(float v, __nv_bfloat16& hi, __nv_bfloat16& lo) {
    hi = __float2bfloat16(v);
    lo = __float2bfloat16(v - __bfloat162float(hi));
}

__device__ __forceinline__ void cp16(uint32_t dst, const void* src) {
    asm volatile("cp.async.ca.shared.global [%0], [%1], 16;" :: "r"(dst), "l"(src));
}

// ---------------------------------------------------------------------------
// prep_B: combined transposed weights B[g][n][k] (k contiguous), bf16 hi/lo.
//   g 0..3 : W[g] (k<128), g 4..8 : Ubin[g-4] (k<256), g 9..12: Uun[g-9] (k<128)
// ---------------------------------------------------------------------------
__global__ void prep_B_kernel(const float* __restrict__ W,
                              const float* __restrict__ Ubin,
                              const float* __restrict__ Uun)
{
    const int idx = blockIdx.x * 256 + threadIdx.x;
    if (idx >= 13 * 128 * 256) return;
    const int g = idx >> 15;
    const int n = (idx >> 8) & 127;
    const int k = idx & 255;
    float v;
    if (g < 4)       v = (k < 128) ? W[g * 16384 + k * 128 + n] : 0.f;
    else if (g < 9)  v = Ubin[(g - 4) * 32768 + k * 128 + n];
    else             v = (k < 128) ? Uun[(g - 9) * 16384 + k * 128 + n] : 0.f;
    split_bf16(v, g_Bc_hi[idx], g_Bc_lo[idx]);
}

__global__ void stage_leaf_kernel(const int* __restrict__ tokens,
                                  const float* __restrict__ emb)
{
    const int idx = blockIdx.x * 256 + threadIdx.x;
    const int row = idx >> 7;
    const int col = idx & 127;
    const int b = row >> 8, n = row & 255;
    const int tok = __ldg(&tokens[b * NTOK + 255 + n]);
    const float v = __ldg(&emb[(size_t)tok * 128 + col]);
    split_bf16(v, g_Aleaf_hi[idx], g_Aleaf_lo[idx]);
}

__global__ void stage_x_kernel(const int* __restrict__ tokens,
                               const float* __restrict__ emb, int l)
{
    const int idx = blockIdx.x * 256 + threadIdx.x;
    const int row = idx >> 7;
    const int col = idx & 127;
    const int b = row >> l;
    const int n = row - (b << l);
    const int tok = __ldg(&tokens[b * NTOK + ((1 << l) - 1) + n]);
    const float v = __ldg(&emb[(size_t)tok * 128 + col]);
    __nv_bfloat16 hi, lo;
    split_bf16(v, hi, lo);
    const size_t o = (size_t)row * 384 + col;
    g_Az_hi[l & 1][o] = hi;
    g_Az_lo[l & 1][o] = lo;
}

// ---------------------------------------------------------------------------
// GEMM via mma.sync m16n8k16 bf16, 3-term split, cp.async double-buffered.
// Block: 128 rows x 1 gate (N=128). 8 warps 2(M)x4(N), warp tile 64x32.
// K-chunk = 32. smem: sbuf[2 buf][2 arr][128][40] bf16 = 40KB.
// mode 0: gates -> gbuf (fp16). mode 1 (leaf): tanh+bias -> level-7 Az, c=0.
// ---------------------------------------------------------------------------
__global__ __launch_bounds__(256, 2)
void gemm_kernel(int mode, int azi, const float* __restrict__ bW)
{
    __shared__ __align__(16) __nv_bfloat16 sbuf[2][2][128][40];

    const int tid  = threadIdx.x;
    const int wid  = tid >> 5;
    const int lane = tid & 31;
    const int grp  = lane >> 2;
    const int tig  = lane & 3;
    const int wm   = wid & 1;
    const int wn   = wid >> 1;
    const int g    = (mode == 1) ? 3 : (int)blockIdx.y;
    const int row0 = blockIdx.x * 128;

    const __nv_bfloat16* Ah = (mode == 1) ? g_Aleaf_hi : g_Az_hi[azi];
    const __nv_bfloat16* Al = (mode == 1) ? g_Aleaf_lo : g_Az_lo[azi];
    const int astride = (mode == 1) ? 128 : 384;
    int nchp, akb;                      // nch = 1<<nchp chunks of K=32 per term
    if (mode == 1 || g < 4) { nchp = 2; akb = 0;   }   // K=128 (x)
    else if (g < 9)         { nchp = 3; akb = 128; }   // K=256 (hcat)
    else                    { nchp = 2; akb = 128; }   // K=128 (h_l)
    const int nch = 1 << nchp;
    const int NCH = 3 * nch;
    const size_t gbase = (size_t)g * 32768;

    float acc[4][4][4];
#pragma unroll
    for (int i = 0; i < 4; i++)
#pragma unroll
        for (int j = 0; j < 4; j++)
#pragma unroll
            for (int q = 0; q < 4; q++) acc[i][j][q] = 0.f;

    const uint32_t sbase = (uint32_t)__cvta_generic_to_shared(&sbuf[0][0][0][0]);
    const int srow  = tid >> 1;          // staging row 0..127
    const int shalf = tid & 1;           // 16-elem half of the 32-elem chunk row

    // issue chunk ci into buffer buf
    auto issue = [&](int ci, int buf) {
        const int t = ci >> nchp;
        const int c = ci & (nch - 1);
        const __nv_bfloat16* As = (t == 1) ? Al : Ah;
        const __nv_bfloat16* Bs = (t == 2) ? g_Bc_lo : g_Bc_hi;
        const __nv_bfloat16* ap =
            As + (size_t)(row0 + srow) * astride + akb + c * 32 + shalf * 16;
        const __nv_bfloat16* bp =
            Bs + gbase + (size_t)srow * 256 + c * 32 + shalf * 16;
        const uint32_t da = sbase + (uint32_t)((buf * 2 + 0) * 10240 + srow * 80 + shalf * 32);
        const uint32_t db = sbase + (uint32_t)((buf * 2 + 1) * 10240 + srow * 80 + shalf * 32);
        cp16(da,      ap);
        cp16(da + 16, (const char*)ap + 16);
        cp16(db,      bp);
        cp16(db + 16, (const char*)bp + 16);
        asm volatile("cp.async.commit_group;" ::: "memory");
    };

    issue(0, 0);
    for (int ci = 0; ci < NCH; ci++) {
        if (ci + 1 < NCH) {
            issue(ci + 1, (ci + 1) & 1);
            asm volatile("cp.async.wait_group 1;" ::: "memory");
        } else {
            asm volatile("cp.async.wait_group 0;" ::: "memory");
        }
        __syncthreads();

        const int buf = ci & 1;
#pragma unroll
        for (int ks = 0; ks < 2; ks++) {
            const int k0 = ks * 16;
            uint32_t a[4][4], b[4][2];
#pragma unroll
            for (int i = 0; i < 4; i++) {
                const int r = wm * 64 + i * 16 + grp;
                a[i][0] = *(const uint32_t*)&sbuf[buf][0][r    ][k0 + tig * 2];
                a[i][1] = *(const uint32_t*)&sbuf[buf][0][r + 8][k0 + tig * 2];
                a[i][2] = *(const uint32_t*)&sbuf[buf][0][r    ][k0 + 8 + tig * 2];
                a[i][3] = *(const uint32_t*)&sbuf[buf][0][r + 8][k0 + 8 + tig * 2];
            }
#pragma unroll
            for (int j = 0; j < 4; j++) {
                const int n = wn * 32 + j * 8 + grp;
                b[j][0] = *(const uint32_t*)&sbuf[buf][1][n][k0 + tig * 2];
                b[j][1] = *(const uint32_t*)&sbuf[buf][1][n][k0 + 8 + tig * 2];
            }
#pragma unroll
            for (int i = 0; i < 4; i++)
#pragma unroll
                for (int j = 0; j < 4; j++)
                    asm volatile(
                        "mma.sync.aligned.m16n8k16.row.col.f32.bf16.bf16.f32 "
                        "{%0,%1,%2,%3}, {%4,%5,%6,%7}, {%8,%9}, {%0,%1,%2,%3};"
                        : "+f"(acc[i][j][0]), "+f"(acc[i][j][1]),
                          "+f"(acc[i][j][2]), "+f"(acc[i][j][3])
                        : "r"(a[i][0]), "r"(a[i][1]), "r"(a[i][2]), "r"(a[i][3]),
                          "r"(b[j][0]), "r"(b[j][1]));
        }
        __syncthreads();   // protect buffer reuse by next issue
    }

    // ---- Epilogue ----
    if (mode == 0) {
        const int gcb = g * 128 + wn * 32;
#pragma unroll
        for (int i = 0; i < 4; i++) {
            const int r = row0 + wm * 64 + i * 16 + grp;
#pragma unroll
            for (int j = 0; j < 4; j++) {
                const int col = gcb + j * 8 + tig * 2;
                *(__half2*)&g_gbuf[(size_t)r * 1664 + col] =
                    __floats2half2_rn(acc[i][j][0], acc[i][j][1]);
                *(__half2*)&g_gbuf[(size_t)(r + 8) * 1664 + col] =
                    __floats2half2_rn(acc[i][j][2], acc[i][j][3]);
            }
        }
    } else {
        // Leaf: h = tanh(acc + bW[3]); scatter into level-7 Az h-slots; c = 0.
#pragma unroll
        for (int j = 0; j < 4; j++) {
            const int col = wn * 32 + j * 8 + tig * 2;
            const float b0 = __ldg(&bW[384 + col]);
            const float b1 = __ldg(&bW[384 + col + 1]);
#pragma unroll
            for (int i = 0; i < 4; i++) {
#pragma unroll
                for (int half = 0; half < 2; half++) {
                    const int lr = row0 + wm * 64 + i * 16 + grp + half * 8;
                    const float h0 = tanh_(acc[i][j][half * 2 + 0] + b0);
                    const float h1 = tanh_(acc[i][j][half * 2 + 1] + b1);
                    const int bb = lr >> 8, nn = lr & 255;
                    const int prow = (bb << 7) + (nn >> 1);
                    const int side = nn & 1;
                    const size_t o = (size_t)prow * 384 + 128 + side * 128 + col;
                    __nv_bfloat16 hi0, lo0, hi1, lo1;
                    split_bf16(h0, hi0, lo0);
                    split_bf16(h1, hi1, lo1);
                    __nv_bfloat162 vh; vh.x = hi0; vh.y = hi1;
                    __nv_bfloat162 vl; vl.x = lo0; vl.y = lo1;
                    *(__nv_bfloat162*)&g_Az_hi[1][o] = vh;
                    *(__nv_bfloat162*)&g_Az_lo[1][o] = vl;
                    *(float2*)&g_cbuf[0][(size_t)lr * 128 + col] = make_float2(0.f, 0.f);
                }
            }
        }
    }
}

// ---------------------------------------------------------------------------
// Pointwise LSTM cell update for level l.
// ---------------------------------------------------------------------------
__global__ __launch_bounds__(128)
void pointwise_kernel(int l, int cin,
                      const int* __restrict__ arity,
                      const float* __restrict__ bW,
                      const float* __restrict__ bUbin,
                      const float* __restrict__ bUun,
                      float* __restrict__ out)
{
    const int row = blockIdx.x;
    const int col = threadIdx.x;
    const int b = row >> l;
    const int n = row - (b << l);
    const int ar = __ldg(&arity[b * NARITY + ((1 << l) - 1) + n]);
    const size_t childrow = ((size_t)b << (l + 1)) + 2 * n;
    const float cl = g_cbuf[cin][childrow * 128 + col];
    const float cr = g_cbuf[cin][(childrow + 1) * 128 + col];
    const __half* gb = g_gbuf + (size_t)row * 1664;

    const float wx0 = __half2float(gb[0 * 128 + col]) + __ldg(&bW[0 * 128 + col]);
    const float wx1 = __half2float(gb[1 * 128 + col]) + __ldg(&bW[1 * 128 + col]);
    const float wx2 = __half2float(gb[2 * 128 + col]) + __ldg(&bW[2 * 128 + col]);
    const float wx3 = __half2float(gb[3 * 128 + col]) + __ldg(&bW[3 * 128 + col]);

    float hv, cv;
    if (ar == 1) {
        const float ig = sigmoid_(wx0 + __half2float(gb[4 * 128 + col]) + __ldg(&bUbin[0 * 128 + col]));
        const float fl = sigmoid_(wx1 + __half2float(gb[5 * 128 + col]) + __ldg(&bUbin[1 * 128 + col]));
        const float fr = sigmoid_(wx1 + __half2float(gb[6 * 128 + col]) + __ldg(&bUbin[2 * 128 + col]));
        const float og = sigmoid_(wx2 + __half2float(gb[7 * 128 + col]) + __ldg(&bUbin[3 * 128 + col]));
        const float ug = tanh_   (wx3 + __half2float(gb[8 * 128 + col]) + __ldg(&bUbin[4 * 128 + col]));
        cv = ig * ug + fl * cl + fr * cr;
        hv = og * tanh_(cv);
    } else {
        const float ig = sigmoid_(wx0 + __half2float(gb[ 9 * 128 + col]) + __ldg(&bUun[0 * 128 + col]));
        const float fg = sigmoid_(wx1 + __half2float(gb[10 * 128 + col]) + __ldg(&bUun[1 * 128 + col]));
        const float og = sigmoid_(wx2 + __half2float(gb[11 * 128 + col]) + __ldg(&bUun[2 * 128 + col]));
        const float ug = tanh_   (wx3 + __half2float(gb[12 * 128 + col]) + __ldg(&bUun[3 * 128 + col]));
        cv = ig * ug + fg * cl;
        hv = og * tanh_(cv);
    }

    g_cbuf[1 - cin][(size_t)row * 128 + col] = cv;

    if (l == 0) {
        out[row * 128 + col] = hv;
        out[BATCH * HDIM + row * 128 + col] = cv;
    } else {
        const int prow = (b << (l - 1)) + (n >> 1);
        const int side = n & 1;
        __nv_bfloat16 hi, lo;
        split_bf16(hv, hi, lo);
        const size_t o = (size_t)prow * 384 + 128 + side * 128 + col;
        g_Az_hi[(l - 1) & 1][o] = hi;
        g_Az_lo[(l - 1) & 1][o] = lo;
    }
}

// ---------------------------------------------------------------------------
extern "C" void kernel_launch(void* const* d_in, const int* in_sizes, int n_in,
                              void* d_out, int out_size)
{
    const int*   tokens = (const int*)  d_in[0];
    const int*   arity  = (const int*)  d_in[1];
    const float* emb    = (const float*)d_in[2];
    const float* W      = (const float*)d_in[3];
    const float* bW     = (const float*)d_in[4];
    const float* Ubin   = (const float*)d_in[5];
    const float* bUbin  = (const float*)d_in[6];
    const float* Uun    = (const float*)d_in[7];
    const float* bUun   = (const float*)d_in[8];
    float* out = (float*)d_out;

    prep_B_kernel<<<(13 * 128 * 256 + 255) / 256, 256>>>(W, Ubin, Uun);
    stage_leaf_kernel<<<(65536 * 128) / 256, 256>>>(tokens, emb);

    // Leaf GEMM (gate 3 = W[3])
    {
        dim3 grid(65536 / 128, 1);
        gemm_kernel<<<grid, 256>>>(1, 0, bW);
    }

    // Levels 7..0
    for (int l = 7; l >= 0; l--) {
        const int rows = BATCH << l;
        const int cin = (7 - l) & 1;
        stage_x_kernel<<<(rows * 128) / 256, 256>>>(tokens, emb, l);
        dim3 ggrid(rows / 128, 13);
        gemm_kernel<<<ggrid, 256>>>(0, l & 1, bW);
        pointwise_kernel<<<rows, 128>>>(l, cin, arity, bW, bUbin, bUun,
                                        (l == 0) ? out : nullptr);
    }
}

// round 8
// speedup vs baseline: 2.4850x; 1.4092x over previous
#include <cuda_runtime.h>
#include <cuda_fp16.h>
#include <cstdint>
#include <math.h>

#define BATCH 256
#define HDIM  128
#define NTOK  511
#define NARITY 255

// ---------------------------------------------------------------------------
// Static device scratch:
//   Bc   : combined transposed weights [13 gates][n=128][k=256] fp16 (single)
//   Aleaf: leaf embeddings [65536][128] fp16 hi/lo (2-term split)
//   Az   : per-level inputs [2 ping-pong][32768 rows][384 k] fp16 hi/lo
//   gbuf : gate pre-activations [32768][13*128] fp16
//   cbuf : cell-state ping-pong [2][65536][128] fp32
// ---------------------------------------------------------------------------
__device__ __align__(16) __half g_Bc[13 * 128 * 256];
__device__ __align__(16) __half g_Aleaf_hi[65536 * 128];
__device__ __align__(16) __half g_Aleaf_lo[65536 * 128];
__device__ __align__(16) __half g_Az_hi[2][32768 * 384];
__device__ __align__(16) __half g_Az_lo[2][32768 * 384];
__device__ __align__(16) __half g_gbuf[32768 * 1664];
__device__ __align__(16) float  g_cbuf[2][65536 * 128];

__device__ __forceinline__ float sigmoid_(float x) { return 1.0f / (1.0f + expf(-x)); }
__device__ __forceinline__ float tanh_(float x)    { return 1.0f - 2.0f / (expf(2.0f * x) + 1.0f); }

__device__ __forceinline__ void split_fp16(float v, __half& hi, __half& lo) {
    hi = __float2half_rn(v);
    lo = __float2half_rn(v - __half2float(hi));
}

__device__ __forceinline__ void cp16(uint32_t dst, const void* src) {
    asm volatile("cp.async.ca.shared.global [%0], [%1], 16;" :: "r"(dst), "l"(src));
}

// ---------------------------------------------------------------------------
// prep_B: combined transposed weights B[g][n][k] (k contiguous), fp16.
//   g 0..3 : W[g] (k<128), g 4..8 : Ubin[g-4] (k<256), g 9..12: Uun[g-9] (k<128)
// ---------------------------------------------------------------------------
__global__ void prep_B_kernel(const float* __restrict__ W,
                              const float* __restrict__ Ubin,
                              const float* __restrict__ Uun)
{
    const int idx = blockIdx.x * 256 + threadIdx.x;
    if (idx >= 13 * 128 * 256) return;
    const int g = idx >> 15;
    const int n = (idx >> 8) & 127;
    const int k = idx & 255;
    float v;
    if (g < 4)       v = (k < 128) ? W[g * 16384 + k * 128 + n] : 0.f;
    else if (g < 9)  v = Ubin[(g - 4) * 32768 + k * 128 + n];
    else             v = (k < 128) ? Uun[(g - 9) * 16384 + k * 128 + n] : 0.f;
    g_Bc[idx] = __float2half_rn(v);
}

__global__ void stage_leaf_kernel(const int* __restrict__ tokens,
                                  const float* __restrict__ emb)
{
    const int idx = blockIdx.x * 256 + threadIdx.x;
    const int row = idx >> 7;
    const int col = idx & 127;
    const int b = row >> 8, n = row & 255;
    const int tok = __ldg(&tokens[b * NTOK + 255 + n]);
    const float v = __ldg(&emb[(size_t)tok * 128 + col]);
    split_fp16(v, g_Aleaf_hi[idx], g_Aleaf_lo[idx]);
}

__global__ void stage_x_kernel(const int* __restrict__ tokens,
                               const float* __restrict__ emb, int l)
{
    const int idx = blockIdx.x * 256 + threadIdx.x;
    const int row = idx >> 7;
    const int col = idx & 127;
    const int b = row >> l;
    const int n = row - (b << l);
    const int tok = __ldg(&tokens[b * NTOK + ((1 << l) - 1) + n]);
    const float v = __ldg(&emb[(size_t)tok * 128 + col]);
    __half hi, lo;
    split_fp16(v, hi, lo);
    const size_t o = (size_t)row * 384 + col;
    g_Az_hi[l & 1][o] = hi;
    g_Az_lo[l & 1][o] = lo;
}

// ---------------------------------------------------------------------------
// GEMM via mma.sync m16n8k16 fp16 (A 2-term hi/lo split, B single fp16).
// Block: 64 rows x 1 gate (N=128). 8 warps 2(M)x4(N), warp tile 32x32.
// K-chunk = 32, cp.async double-buffered; B staged once per chunk, shared by
// both A terms. smem = sA[2 buf][2 term][64][40] + sB[2 buf][128][40] = 40KB.
// mode 0: gates -> gbuf (fp16). mode 1 (leaf): tanh+bias -> level-7 Az, c=0.
// ---------------------------------------------------------------------------
__global__ __launch_bounds__(256, 2)
void gemm_kernel(int mode, int azi, const float* __restrict__ bW)
{
    __shared__ __align__(16) __half sA[2][2][64][40];
    __shared__ __align__(16) __half sB[2][128][40];

    const int tid  = threadIdx.x;
    const int wid  = tid >> 5;
    const int lane = tid & 31;
    const int grp  = lane >> 2;
    const int tig  = lane & 3;
    const int wm   = wid & 1;          // M warp (0..1), 32 rows each
    const int wn   = wid >> 1;         // N warp (0..3), 32 cols each
    const int g    = (mode == 1) ? 3 : (int)blockIdx.x;
    const int row0 = (int)blockIdx.y * 64;

    const __half* Ah = (mode == 1) ? g_Aleaf_hi : g_Az_hi[azi];
    const __half* Al = (mode == 1) ? g_Aleaf_lo : g_Az_lo[azi];
    const int astride = (mode == 1) ? 128 : 384;
    int nch, akb;
    if (mode == 1 || g < 4) { nch = 4; akb = 0;   }   // K=128 (x)
    else if (g < 9)         { nch = 8; akb = 128; }   // K=256 (hcat)
    else                    { nch = 4; akb = 128; }   // K=128 (h_l)
    const size_t gbase = (size_t)g * 32768;

    float acc[2][4][4];
#pragma unroll
    for (int i = 0; i < 2; i++)
#pragma unroll
        for (int j = 0; j < 4; j++)
#pragma unroll
            for (int q = 0; q < 4; q++) acc[i][j][q] = 0.f;

    // IMPORTANT: derive each shared array's address from ITS OWN symbol —
    // placement order of distinct __shared__ arrays is not guaranteed.
    const uint32_t sabase = (uint32_t)__cvta_generic_to_shared(&sA[0][0][0][0]);
    const uint32_t sbbase = (uint32_t)__cvta_generic_to_shared(&sB[0][0][0]);
    const int arow = tid >> 2;           // 0..63
    const int aseg = tid & 3;            // 16B segment within 64B chunk-row
    const int brow = tid >> 1;           // 0..127
    const int bseg = (tid & 1) * 2;      // two consecutive 16B segments

    auto issue = [&](int c, int buf) {
        const __half* aph = Ah + (size_t)(row0 + arow) * astride + akb + c * 32 + aseg * 8;
        const __half* apl = Al + (size_t)(row0 + arow) * astride + akb + c * 32 + aseg * 8;
        const __half* bp  = g_Bc + gbase + (size_t)brow * 256 + c * 32 + bseg * 8;
        const uint32_t da = sabase + (uint32_t)(((buf * 2 + 0) * 64 + arow) * 80 + aseg * 16);
        const uint32_t dl = sabase + (uint32_t)(((buf * 2 + 1) * 64 + arow) * 80 + aseg * 16);
        const uint32_t db = sbbase + (uint32_t)((buf * 128 + brow) * 80 + bseg * 16);
        cp16(da, aph);
        cp16(dl, apl);
        cp16(db,      bp);
        cp16(db + 16, (const char*)bp + 16);
        asm volatile("cp.async.commit_group;" ::: "memory");
    };

    issue(0, 0);
    for (int ci = 0; ci < nch; ci++) {
        if (ci + 1 < nch) {
            issue(ci + 1, (ci + 1) & 1);
            asm volatile("cp.async.wait_group 1;" ::: "memory");
        } else {
            asm volatile("cp.async.wait_group 0;" ::: "memory");
        }
        __syncthreads();

        const int buf = ci & 1;
#pragma unroll
        for (int ks = 0; ks < 2; ks++) {
            const int k0 = ks * 16;
            uint32_t b[4][2];
#pragma unroll
            for (int j = 0; j < 4; j++) {
                const int n = wn * 32 + j * 8 + grp;
                b[j][0] = *(const uint32_t*)&sB[buf][n][k0 + tig * 2];
                b[j][1] = *(const uint32_t*)&sB[buf][n][k0 + 8 + tig * 2];
            }
#pragma unroll
            for (int p = 0; p < 2; p++) {   // A term: hi, lo
                uint32_t a[2][4];
#pragma unroll
                for (int i = 0; i < 2; i++) {
                    const int r = wm * 32 + i * 16 + grp;
                    a[i][0] = *(const uint32_t*)&sA[buf][p][r    ][k0 + tig * 2];
                    a[i][1] = *(const uint32_t*)&sA[buf][p][r + 8][k0 + tig * 2];
                    a[i][2] = *(const uint32_t*)&sA[buf][p][r    ][k0 + 8 + tig * 2];
                    a[i][3] = *(const uint32_t*)&sA[buf][p][r + 8][k0 + 8 + tig * 2];
                }
#pragma unroll
                for (int i = 0; i < 2; i++)
#pragma unroll
                    for (int j = 0; j < 4; j++)
                        asm volatile(
                            "mma.sync.aligned.m16n8k16.row.col.f32.f16.f16.f32 "
                            "{%0,%1,%2,%3}, {%4,%5,%6,%7}, {%8,%9}, {%0,%1,%2,%3};"
                            : "+f"(acc[i][j][0]), "+f"(acc[i][j][1]),
                              "+f"(acc[i][j][2]), "+f"(acc[i][j][3])
                            : "r"(a[i][0]), "r"(a[i][1]), "r"(a[i][2]), "r"(a[i][3]),
                              "r"(b[j][0]), "r"(b[j][1]));
            }
        }
        __syncthreads();   // protect buffer reuse by the next issue
    }

    // ---- Epilogue ----
    if (mode == 0) {
        const int gcb = g * 128 + wn * 32;
#pragma unroll
        for (int i = 0; i < 2; i++) {
            const int r = row0 + wm * 32 + i * 16 + grp;
#pragma unroll
            for (int j = 0; j < 4; j++) {
                const int col = gcb + j * 8 + tig * 2;
                *(__half2*)&g_gbuf[(size_t)r * 1664 + col] =
                    __floats2half2_rn(acc[i][j][0], acc[i][j][1]);
                *(__half2*)&g_gbuf[(size_t)(r + 8) * 1664 + col] =
                    __floats2half2_rn(acc[i][j][2], acc[i][j][3]);
            }
        }
    } else {
        // Leaf: h = tanh(acc + bW[3]); scatter into level-7 Az h-slots; c = 0.
#pragma unroll
        for (int j = 0; j < 4; j++) {
            const int col = wn * 32 + j * 8 + tig * 2;
            const float b0 = __ldg(&bW[384 + col]);
            const float b1 = __ldg(&bW[384 + col + 1]);
#pragma unroll
            for (int i = 0; i < 2; i++) {
#pragma unroll
                for (int half = 0; half < 2; half++) {
                    const int lr = row0 + wm * 32 + i * 16 + grp + half * 8;
                    const float h0 = tanh_(acc[i][j][half * 2 + 0] + b0);
                    const float h1 = tanh_(acc[i][j][half * 2 + 1] + b1);
                    const int bb = lr >> 8, nn = lr & 255;
                    const int prow = (bb << 7) + (nn >> 1);
                    const int side = nn & 1;
                    const size_t o = (size_t)prow * 384 + 128 + side * 128 + col;
                    __half hi0, lo0, hi1, lo1;
                    split_fp16(h0, hi0, lo0);
                    split_fp16(h1, hi1, lo1);
                    __half2 vh; vh.x = hi0; vh.y = hi1;
                    __half2 vl; vl.x = lo0; vl.y = lo1;
                    *(__half2*)&g_Az_hi[1][o] = vh;
                    *(__half2*)&g_Az_lo[1][o] = vl;
                    *(float2*)&g_cbuf[0][(size_t)lr * 128 + col] = make_float2(0.f, 0.f);
                }
            }
        }
    }
}

// ---------------------------------------------------------------------------
// Pointwise LSTM cell update for level l.
// ---------------------------------------------------------------------------
__global__ __launch_bounds__(128)
void pointwise_kernel(int l, int cin,
                      const int* __restrict__ arity,
                      const float* __restrict__ bW,
                      const float* __restrict__ bUbin,
                      const float* __restrict__ bUun,
                      float* __restrict__ out)
{
    const int row = blockIdx.x;
    const int col = threadIdx.x;
    const int b = row >> l;
    const int n = row - (b << l);
    const int ar = __ldg(&arity[b * NARITY + ((1 << l) - 1) + n]);
    const size_t childrow = ((size_t)b << (l + 1)) + 2 * n;
    const float cl = g_cbuf[cin][childrow * 128 + col];
    const float cr = g_cbuf[cin][(childrow + 1) * 128 + col];
    const __half* gb = g_gbuf + (size_t)row * 1664;

    const float wx0 = __half2float(gb[0 * 128 + col]) + __ldg(&bW[0 * 128 + col]);
    const float wx1 = __half2float(gb[1 * 128 + col]) + __ldg(&bW[1 * 128 + col]);
    const float wx2 = __half2float(gb[2 * 128 + col]) + __ldg(&bW[2 * 128 + col]);
    const float wx3 = __half2float(gb[3 * 128 + col]) + __ldg(&bW[3 * 128 + col]);

    float hv, cv;
    if (ar == 1) {
        const float ig = sigmoid_(wx0 + __half2float(gb[4 * 128 + col]) + __ldg(&bUbin[0 * 128 + col]));
        const float fl = sigmoid_(wx1 + __half2float(gb[5 * 128 + col]) + __ldg(&bUbin[1 * 128 + col]));
        const float fr = sigmoid_(wx1 + __half2float(gb[6 * 128 + col]) + __ldg(&bUbin[2 * 128 + col]));
        const float og = sigmoid_(wx2 + __half2float(gb[7 * 128 + col]) + __ldg(&bUbin[3 * 128 + col]));
        const float ug = tanh_   (wx3 + __half2float(gb[8 * 128 + col]) + __ldg(&bUbin[4 * 128 + col]));
        cv = ig * ug + fl * cl + fr * cr;
        hv = og * tanh_(cv);
    } else {
        const float ig = sigmoid_(wx0 + __half2float(gb[ 9 * 128 + col]) + __ldg(&bUun[0 * 128 + col]));
        const float fg = sigmoid_(wx1 + __half2float(gb[10 * 128 + col]) + __ldg(&bUun[1 * 128 + col]));
        const float og = sigmoid_(wx2 + __half2float(gb[11 * 128 + col]) + __ldg(&bUun[2 * 128 + col]));
        const float ug = tanh_   (wx3 + __half2float(gb[12 * 128 + col]) + __ldg(&bUun[3 * 128 + col]));
        cv = ig * ug + fg * cl;
        hv = og * tanh_(cv);
    }

    g_cbuf[1 - cin][(size_t)row * 128 + col] = cv;

    if (l == 0) {
        out[row * 128 + col] = hv;
        out[BATCH * HDIM + row * 128 + col] = cv;
    } else {
        const int prow = (b << (l - 1)) + (n >> 1);
        const int side = n & 1;
        __half hi, lo;
        split_fp16(hv, hi, lo);
        const size_t o = (size_t)prow * 384 + 128 + side * 128 + col;
        g_Az_hi[(l - 1) & 1][o] = hi;
        g_Az_lo[(l - 1) & 1][o] = lo;
    }
}

// ---------------------------------------------------------------------------
extern "C" void kernel_launch(void* const* d_in, const int* in_sizes, int n_in,
                              void* d_out, int out_size)
{
    const int*   tokens = (const int*)  d_in[0];
    const int*   arity  = (const int*)  d_in[1];
    const float* emb    = (const float*)d_in[2];
    const float* W      = (const float*)d_in[3];
    const float* bW     = (const float*)d_in[4];
    const float* Ubin   = (const float*)d_in[5];
    const float* bUbin  = (const float*)d_in[6];
    const float* Uun    = (const float*)d_in[7];
    const float* bUun   = (const float*)d_in[8];
    float* out = (float*)d_out;

    prep_B_kernel<<<(13 * 128 * 256 + 255) / 256, 256>>>(W, Ubin, Uun);
    stage_leaf_kernel<<<(65536 * 128) / 256, 256>>>(tokens, emb);

    // Leaf GEMM (gate 3 = W[3])
    {
        dim3 grid(1, 65536 / 64);
        gemm_kernel<<<grid, 256>>>(1, 0, bW);
    }

    // Levels 7..0
    for (int l = 7; l >= 0; l--) {
        const int rows = BATCH << l;
        const int cin = (7 - l) & 1;
        stage_x_kernel<<<(rows * 128) / 256, 256>>>(tokens, emb, l);
        dim3 ggrid(13, rows / 64);
        gemm_kernel<<<ggrid, 256>>>(0, l & 1, bW);
        pointwise_kernel<<<rows, 128>>>(l, cin, arity, bW, bUbin, bUun,
                                        (l == 0) ? out : nullptr);
    }
}

// round 9
// speedup vs baseline: 3.2239x; 1.2973x over previous
#include <cuda_runtime.h>
#include <cuda_fp16.h>
#include <cstdint>
#include <math.h>

#define BATCH 256
#define HDIM  128
#define NTOK  511
#define NARITY 255

// ---------------------------------------------------------------------------
// Static device scratch:
//   Bc   : combined transposed weights [13 gates][n=128][k=256] fp16
//   Aleaf: leaf embeddings [65536][128] fp16
//   Az   : per-level inputs [2 ping-pong][32768 rows][384 k] fp16
//          (k layout: x 0..127, h_l 128..255, h_r 256..383)
//   gbuf : gate pre-activations [32768][13*128] fp16
//   cbuf : cell-state ping-pong [2][65536][128] fp32
// ---------------------------------------------------------------------------
__device__ __align__(16) __half g_Bc[13 * 128 * 256];
__device__ __align__(16) __half g_Aleaf[65536 * 128];
__device__ __align__(16) __half g_Az[2][32768 * 384];
__device__ __align__(16) __half g_gbuf[32768 * 1664];
__device__ __align__(16) float  g_cbuf[2][65536 * 128];

__device__ __forceinline__ float sigmoid_(float x) { return 1.0f / (1.0f + expf(-x)); }
__device__ __forceinline__ float tanh_(float x)    { return 1.0f - 2.0f / (expf(2.0f * x) + 1.0f); }

__device__ __forceinline__ void cp16(uint32_t dst, const void* src) {
    asm volatile("cp.async.ca.shared.global [%0], [%1], 16;" :: "r"(dst), "l"(src));
}

// ---------------------------------------------------------------------------
// prep_B: combined transposed weights B[g][n][k] (k contiguous), fp16.
//   g 0..3 : W[g] (k<128), g 4..8 : Ubin[g-4] (k<256), g 9..12: Uun[g-9] (k<128)
// ---------------------------------------------------------------------------
__global__ void prep_B_kernel(const float* __restrict__ W,
                              const float* __restrict__ Ubin,
                              const float* __restrict__ Uun)
{
    const int idx = blockIdx.x * 256 + threadIdx.x;
    if (idx >= 13 * 128 * 256) return;
    const int g = idx >> 15;
    const int n = (idx >> 8) & 127;
    const int k = idx & 255;
    float v;
    if (g < 4)       v = (k < 128) ? W[g * 16384 + k * 128 + n] : 0.f;
    else if (g < 9)  v = Ubin[(g - 4) * 32768 + k * 128 + n];
    else             v = (k < 128) ? Uun[(g - 9) * 16384 + k * 128 + n] : 0.f;
    g_Bc[idx] = __float2half_rn(v);
}

__global__ void stage_leaf_kernel(const int* __restrict__ tokens,
                                  const float* __restrict__ emb)
{
    const int idx = blockIdx.x * 256 + threadIdx.x;
    const int row = idx >> 7;
    const int col = idx & 127;
    const int b = row >> 8, n = row & 255;
    const int tok = __ldg(&tokens[b * NTOK + 255 + n]);
    g_Aleaf[idx] = __float2half_rn(__ldg(&emb[(size_t)tok * 128 + col]));
}

__global__ void stage_x_kernel(const int* __restrict__ tokens,
                               const float* __restrict__ emb, int l)
{
    const int idx = blockIdx.x * 256 + threadIdx.x;
    const int row = idx >> 7;
    const int col = idx & 127;
    const int b = row >> l;
    const int n = row - (b << l);
    const int tok = __ldg(&tokens[b * NTOK + ((1 << l) - 1) + n]);
    g_Az[l & 1][(size_t)row * 384 + col] =
        __float2half_rn(__ldg(&emb[(size_t)tok * 128 + col]));
}

// ---------------------------------------------------------------------------
// GEMM via mma.sync m16n8k16 fp16, single-term (pure fp16 A and B).
// Block: 128 rows x 1 gate (N=128). 8 warps 2(M)x4(N), warp tile 64x32.
// K-chunk = 32, cp.async double-buffered.
// smem = sA[2][128][40] + sB[2][128][40] = 40KB.
// mode 0: gates -> gbuf (fp16). mode 1 (leaf): tanh+bias -> level-7 Az, c=0.
// ---------------------------------------------------------------------------
__global__ __launch_bounds__(256, 2)
void gemm_kernel(int mode, int azi, const float* __restrict__ bW)
{
    __shared__ __align__(16) __half sA[2][128][40];
    __shared__ __align__(16) __half sB[2][128][40];

    const int tid  = threadIdx.x;
    const int wid  = tid >> 5;
    const int lane = tid & 31;
    const int grp  = lane >> 2;
    const int tig  = lane & 3;
    const int wm   = wid & 1;          // M warp (0..1), 64 rows each
    const int wn   = wid >> 1;         // N warp (0..3), 32 cols each
    const int g    = (mode == 1) ? 3 : (int)blockIdx.x;
    const int row0 = (int)blockIdx.y * 128;

    const __half* A = (mode == 1) ? g_Aleaf : g_Az[azi];
    const int astride = (mode == 1) ? 128 : 384;
    int nch, akb;
    if (mode == 1 || g < 4) { nch = 4; akb = 0;   }   // K=128 (x)
    else if (g < 9)         { nch = 8; akb = 128; }   // K=256 (hcat)
    else                    { nch = 4; akb = 128; }   // K=128 (h_l)
    const size_t gbase = (size_t)g * 32768;

    float acc[4][4][4];
#pragma unroll
    for (int i = 0; i < 4; i++)
#pragma unroll
        for (int j = 0; j < 4; j++)
#pragma unroll
            for (int q = 0; q < 4; q++) acc[i][j][q] = 0.f;

    // Address each shared array from its OWN symbol (placement not guaranteed).
    const uint32_t sabase = (uint32_t)__cvta_generic_to_shared(&sA[0][0][0]);
    const uint32_t sbbase = (uint32_t)__cvta_generic_to_shared(&sB[0][0][0]);
    const int srow = tid >> 1;            // 0..127
    const int sseg = (tid & 1) * 2;       // 2 of 4 16B segments per 64B row

    auto issue = [&](int c, int buf) {
        const __half* ap = A + (size_t)(row0 + srow) * astride + akb + c * 32 + sseg * 8;
        const __half* bp = g_Bc + gbase + (size_t)srow * 256 + c * 32 + sseg * 8;
        const uint32_t da = sabase + (uint32_t)((buf * 128 + srow) * 80 + sseg * 16);
        const uint32_t db = sbbase + (uint32_t)((buf * 128 + srow) * 80 + sseg * 16);
        cp16(da,      ap);
        cp16(da + 16, (const char*)ap + 16);
        cp16(db,      bp);
        cp16(db + 16, (const char*)bp + 16);
        asm volatile("cp.async.commit_group;" ::: "memory");
    };

    issue(0, 0);
    for (int ci = 0; ci < nch; ci++) {
        if (ci + 1 < nch) {
            issue(ci + 1, (ci + 1) & 1);
            asm volatile("cp.async.wait_group 1;" ::: "memory");
        } else {
            asm volatile("cp.async.wait_group 0;" ::: "memory");
        }
        __syncthreads();

        const int buf = ci & 1;
#pragma unroll
        for (int ks = 0; ks < 2; ks++) {
            const int k0 = ks * 16;
            uint32_t a[4][4], b[4][2];
#pragma unroll
            for (int i = 0; i < 4; i++) {
                const int r = wm * 64 + i * 16 + grp;
                a[i][0] = *(const uint32_t*)&sA[buf][r    ][k0 + tig * 2];
                a[i][1] = *(const uint32_t*)&sA[buf][r + 8][k0 + tig * 2];
                a[i][2] = *(const uint32_t*)&sA[buf][r    ][k0 + 8 + tig * 2];
                a[i][3] = *(const uint32_t*)&sA[buf][r + 8][k0 + 8 + tig * 2];
            }
#pragma unroll
            for (int j = 0; j < 4; j++) {
                const int n = wn * 32 + j * 8 + grp;
                b[j][0] = *(const uint32_t*)&sB[buf][n][k0 + tig * 2];
                b[j][1] = *(const uint32_t*)&sB[buf][n][k0 + 8 + tig * 2];
            }
#pragma unroll
            for (int i = 0; i < 4; i++)
#pragma unroll
                for (int j = 0; j < 4; j++)
                    asm volatile(
                        "mma.sync.aligned.m16n8k16.row.col.f32.f16.f16.f32 "
                        "{%0,%1,%2,%3}, {%4,%5,%6,%7}, {%8,%9}, {%0,%1,%2,%3};"
                        : "+f"(acc[i][j][0]), "+f"(acc[i][j][1]),
                          "+f"(acc[i][j][2]), "+f"(acc[i][j][3])
                        : "r"(a[i][0]), "r"(a[i][1]), "r"(a[i][2]), "r"(a[i][3]),
                          "r"(b[j][0]), "r"(b[j][1]));
        }
        __syncthreads();   // protect buffer reuse by the next issue
    }

    // ---- Epilogue ----
    if (mode == 0) {
        const int gcb = g * 128 + wn * 32;
#pragma unroll
        for (int i = 0; i < 4; i++) {
            const int r = row0 + wm * 64 + i * 16 + grp;
#pragma unroll
            for (int j = 0; j < 4; j++) {
                const int col = gcb + j * 8 + tig * 2;
                *(__half2*)&g_gbuf[(size_t)r * 1664 + col] =
                    __floats2half2_rn(acc[i][j][0], acc[i][j][1]);
                *(__half2*)&g_gbuf[(size_t)(r + 8) * 1664 + col] =
                    __floats2half2_rn(acc[i][j][2], acc[i][j][3]);
            }
        }
    } else {
        // Leaf: h = tanh(acc + bW[3]); scatter into level-7 Az h-slots; c = 0.
#pragma unroll
        for (int j = 0; j < 4; j++) {
            const int col = wn * 32 + j * 8 + tig * 2;
            const float b0 = __ldg(&bW[384 + col]);
            const float b1 = __ldg(&bW[384 + col + 1]);
#pragma unroll
            for (int i = 0; i < 4; i++) {
#pragma unroll
                for (int half = 0; half < 2; half++) {
                    const int lr = row0 + wm * 64 + i * 16 + grp + half * 8;
                    const float h0 = tanh_(acc[i][j][half * 2 + 0] + b0);
                    const float h1 = tanh_(acc[i][j][half * 2 + 1] + b1);
                    const int bb = lr >> 8, nn = lr & 255;
                    const int prow = (bb << 7) + (nn >> 1);
                    const int side = nn & 1;
                    const size_t o = (size_t)prow * 384 + 128 + side * 128 + col;
                    *(__half2*)&g_Az[1][o] = __floats2half2_rn(h0, h1);
                    *(float2*)&g_cbuf[0][(size_t)lr * 128 + col] = make_float2(0.f, 0.f);
                }
            }
        }
    }
}

// ---------------------------------------------------------------------------
// Pointwise LSTM cell update for level l.
// ---------------------------------------------------------------------------
__global__ __launch_bounds__(128)
void pointwise_kernel(int l, int cin,
                      const int* __restrict__ arity,
                      const float* __restrict__ bW,
                      const float* __restrict__ bUbin,
                      const float* __restrict__ bUun,
                      float* __restrict__ out)
{
    const int row = blockIdx.x;
    const int col = threadIdx.x;
    const int b = row >> l;
    const int n = row - (b << l);
    const int ar = __ldg(&arity[b * NARITY + ((1 << l) - 1) + n]);
    const size_t childrow = ((size_t)b << (l + 1)) + 2 * n;
    const float cl = g_cbuf[cin][childrow * 128 + col];
    const float cr = g_cbuf[cin][(childrow + 1) * 128 + col];
    const __half* gb = g_gbuf + (size_t)row * 1664;

    const float wx0 = __half2float(gb[0 * 128 + col]) + __ldg(&bW[0 * 128 + col]);
    const float wx1 = __half2float(gb[1 * 128 + col]) + __ldg(&bW[1 * 128 + col]);
    const float wx2 = __half2float(gb[2 * 128 + col]) + __ldg(&bW[2 * 128 + col]);
    const float wx3 = __half2float(gb[3 * 128 + col]) + __ldg(&bW[3 * 128 + col]);

    float hv, cv;
    if (ar == 1) {
        const float ig = sigmoid_(wx0 + __half2float(gb[4 * 128 + col]) + __ldg(&bUbin[0 * 128 + col]));
        const float fl = sigmoid_(wx1 + __half2float(gb[5 * 128 + col]) + __ldg(&bUbin[1 * 128 + col]));
        const float fr = sigmoid_(wx1 + __half2float(gb[6 * 128 + col]) + __ldg(&bUbin[2 * 128 + col]));
        const float og = sigmoid_(wx2 + __half2float(gb[7 * 128 + col]) + __ldg(&bUbin[3 * 128 + col]));
        const float ug = tanh_   (wx3 + __half2float(gb[8 * 128 + col]) + __ldg(&bUbin[4 * 128 + col]));
        cv = ig * ug + fl * cl + fr * cr;
        hv = og * tanh_(cv);
    } else {
        const float ig = sigmoid_(wx0 + __half2float(gb[ 9 * 128 + col]) + __ldg(&bUun[0 * 128 + col]));
        const float fg = sigmoid_(wx1 + __half2float(gb[10 * 128 + col]) + __ldg(&bUun[1 * 128 + col]));
        const float og = sigmoid_(wx2 + __half2float(gb[11 * 128 + col]) + __ldg(&bUun[2 * 128 + col]));
        const float ug = tanh_   (wx3 + __half2float(gb[12 * 128 + col]) + __ldg(&bUun[3 * 128 + col]));
        cv = ig * ug + fg * cl;
        hv = og * tanh_(cv);
    }

    g_cbuf[1 - cin][(size_t)row * 128 + col] = cv;

    if (l == 0) {
        out[row * 128 + col] = hv;
        out[BATCH * HDIM + row * 128 + col] = cv;
    } else {
        const int prow = (b << (l - 1)) + (n >> 1);
        const int side = n & 1;
        g_Az[(l - 1) & 1][(size_t)prow * 384 + 128 + side * 128 + col] =
            __float2half_rn(hv);
    }
}

// ---------------------------------------------------------------------------
extern "C" void kernel_launch(void* const* d_in, const int* in_sizes, int n_in,
                              void* d_out, int out_size)
{
    const int*   tokens = (const int*)  d_in[0];
    const int*   arity  = (const int*)  d_in[1];
    const float* emb    = (const float*)d_in[2];
    const float* W      = (const float*)d_in[3];
    const float* bW     = (const float*)d_in[4];
    const float* Ubin   = (const float*)d_in[5];
    const float* bUbin  = (const float*)d_in[6];
    const float* Uun    = (const float*)d_in[7];
    const float* bUun   = (const float*)d_in[8];
    float* out = (float*)d_out;

    prep_B_kernel<<<(13 * 128 * 256 + 255) / 256, 256>>>(W, Ubin, Uun);
    stage_leaf_kernel<<<(65536 * 128) / 256, 256>>>(tokens, emb);

    // Leaf GEMM (gate 3 = W[3])
    {
        dim3 grid(1, 65536 / 128);
        gemm_kernel<<<grid, 256>>>(1, 0, bW);
    }

    // Levels 7..0
    for (int l = 7; l >= 0; l--) {
        const int rows = BATCH << l;
        const int cin = (7 - l) & 1;
        stage_x_kernel<<<(rows * 128) / 256, 256>>>(tokens, emb, l);
        dim3 ggrid(13, (rows + 127) / 128);
        gemm_kernel<<<ggrid, 256>>>(0, l & 1, bW);
        pointwise_kernel<<<rows, 128>>>(l, cin, arity, bW, bUbin, bUun,
                                        (l == 0) ? out : nullptr);
    }
}

// round 10
// speedup vs baseline: 3.3063x; 1.0255x over previous
#include <cuda_runtime.h>
#include <cuda_fp16.h>
#include <cstdint>
#include <math.h>

#define BATCH 256
#define HDIM  128
#define NTOK  511
#define NARITY 255

// ---------------------------------------------------------------------------
// Static device scratch:
//   Bc   : combined transposed weights [13 gates][n=128][k=256] fp16
//   Aleaf: leaf embeddings [65536][128] fp16
//   Az   : per-level inputs [2 ping-pong][32768 rows][384 k] fp16
//   gbuf : gate pre-activations [32768][13*128] fp16
//   cbuf : cell-state ping-pong [2][65536][128] fp32
//   list/cnt : per-level arity-compacted row lists (0 = binary, 1 = unary)
// ---------------------------------------------------------------------------
__device__ __align__(16) __half g_Bc[13 * 128 * 256];
__device__ __align__(16) __half g_Aleaf[65536 * 128];
__device__ __align__(16) __half g_Az[2][32768 * 384];
__device__ __align__(16) __half g_gbuf[32768 * 1664];
__device__ __align__(16) float  g_cbuf[2][65536 * 128];
__device__ int g_list[2][32768];
__device__ int g_cnt[2];

__device__ __forceinline__ float sigmoid_(float x) { return 1.0f / (1.0f + expf(-x)); }
__device__ __forceinline__ float tanh_(float x)    { return 1.0f - 2.0f / (expf(2.0f * x) + 1.0f); }

__device__ __forceinline__ void cp16(uint32_t dst, const void* src) {
    asm volatile("cp.async.ca.shared.global [%0], [%1], 16;" :: "r"(dst), "l"(src));
}

// ---------------------------------------------------------------------------
__global__ void prep_B_kernel(const float* __restrict__ W,
                              const float* __restrict__ Ubin,
                              const float* __restrict__ Uun)
{
    const int idx = blockIdx.x * 256 + threadIdx.x;
    if (idx >= 13 * 128 * 256) return;
    const int g = idx >> 15;
    const int n = (idx >> 8) & 127;
    const int k = idx & 255;
    float v;
    if (g < 4)       v = (k < 128) ? W[g * 16384 + k * 128 + n] : 0.f;
    else if (g < 9)  v = Ubin[(g - 4) * 32768 + k * 128 + n];
    else             v = (k < 128) ? Uun[(g - 9) * 16384 + k * 128 + n] : 0.f;
    g_Bc[idx] = __float2half_rn(v);
}

__global__ void stage_leaf_kernel(const int* __restrict__ tokens,
                                  const float* __restrict__ emb)
{
    const int idx = blockIdx.x * 256 + threadIdx.x;
    const int row = idx >> 7;
    const int col = idx & 127;
    const int b = row >> 8, n = row & 255;
    const int tok = __ldg(&tokens[b * NTOK + 255 + n]);
    g_Aleaf[idx] = __float2half_rn(__ldg(&emb[(size_t)tok * 128 + col]));
}

__global__ void stage_x_kernel(const int* __restrict__ tokens,
                               const float* __restrict__ emb, int l)
{
    const int idx = blockIdx.x * 256 + threadIdx.x;
    const int row = idx >> 7;
    const int col = idx & 127;
    const int b = row >> l;
    const int n = row - (b << l);
    const int tok = __ldg(&tokens[b * NTOK + ((1 << l) - 1) + n]);
    g_Az[l & 1][(size_t)row * 384 + col] =
        __float2half_rn(__ldg(&emb[(size_t)tok * 128 + col]));
}

// Arity compaction: reset counters, then classify rows into bin/un lists.
__global__ void reset_kernel() { g_cnt[0] = 0; g_cnt[1] = 0; }

__global__ void classify_kernel(const int* __restrict__ arity, int l, int rows)
{
    const int row = blockIdx.x * 256 + threadIdx.x;
    if (row >= rows) return;
    const int b = row >> l;
    const int n = row - (b << l);
    const int ar = __ldg(&arity[b * NARITY + ((1 << l) - 1) + n]);
    const int w = (ar == 1) ? 0 : 1;
    const int pos = atomicAdd(&g_cnt[w], 1);
    g_list[w][pos] = row;
}

// ---------------------------------------------------------------------------
// Dense GEMM (Wx gates 0..3 over all rows; mode 1 = leaf gate 3).
// mma.sync m16n8k16 fp16, 128 rows x 128 cols, 8 warps 2(M)x4(N).
// ---------------------------------------------------------------------------
__global__ __launch_bounds__(256, 2)
void gemm_kernel(int mode, int azi, const float* __restrict__ bW)
{
    __shared__ __align__(16) __half sA[2][128][40];
    __shared__ __align__(16) __half sB[2][128][40];

    const int tid  = threadIdx.x;
    const int wid  = tid >> 5;
    const int lane = tid & 31;
    const int grp  = lane >> 2;
    const int tig  = lane & 3;
    const int wm   = wid & 1;
    const int wn   = wid >> 1;
    const int g    = (mode == 1) ? 3 : (int)blockIdx.x;   // 0..3
    const int row0 = (int)blockIdx.y * 128;

    const __half* A = (mode == 1) ? g_Aleaf : g_Az[azi];
    const int astride = (mode == 1) ? 128 : 384;
    const int nch = 4;                                    // K=128
    const size_t gbase = (size_t)g * 32768;

    float acc[4][4][4];
#pragma unroll
    for (int i = 0; i < 4; i++)
#pragma unroll
        for (int j = 0; j < 4; j++)
#pragma unroll
            for (int q = 0; q < 4; q++) acc[i][j][q] = 0.f;

    const uint32_t sabase = (uint32_t)__cvta_generic_to_shared(&sA[0][0][0]);
    const uint32_t sbbase = (uint32_t)__cvta_generic_to_shared(&sB[0][0][0]);
    const int srow = tid >> 1;
    const int sseg = (tid & 1) * 2;

    auto issue = [&](int c, int buf) {
        const __half* ap = A + (size_t)(row0 + srow) * astride + c * 32 + sseg * 8;
        const __half* bp = g_Bc + gbase + (size_t)srow * 256 + c * 32 + sseg * 8;
        const uint32_t da = sabase + (uint32_t)((buf * 128 + srow) * 80 + sseg * 16);
        const uint32_t db = sbbase + (uint32_t)((buf * 128 + srow) * 80 + sseg * 16);
        cp16(da,      ap);
        cp16(da + 16, (const char*)ap + 16);
        cp16(db,      bp);
        cp16(db + 16, (const char*)bp + 16);
        asm volatile("cp.async.commit_group;" ::: "memory");
    };

    issue(0, 0);
    for (int ci = 0; ci < nch; ci++) {
        if (ci + 1 < nch) {
            issue(ci + 1, (ci + 1) & 1);
            asm volatile("cp.async.wait_group 1;" ::: "memory");
        } else {
            asm volatile("cp.async.wait_group 0;" ::: "memory");
        }
        __syncthreads();
        const int buf = ci & 1;
#pragma unroll
        for (int ks = 0; ks < 2; ks++) {
            const int k0 = ks * 16;
            uint32_t a[4][4], b[4][2];
#pragma unroll
            for (int i = 0; i < 4; i++) {
                const int r = wm * 64 + i * 16 + grp;
                a[i][0] = *(const uint32_t*)&sA[buf][r    ][k0 + tig * 2];
                a[i][1] = *(const uint32_t*)&sA[buf][r + 8][k0 + tig * 2];
                a[i][2] = *(const uint32_t*)&sA[buf][r    ][k0 + 8 + tig * 2];
                a[i][3] = *(const uint32_t*)&sA[buf][r + 8][k0 + 8 + tig * 2];
            }
#pragma unroll
            for (int j = 0; j < 4; j++) {
                const int n = wn * 32 + j * 8 + grp;
                b[j][0] = *(const uint32_t*)&sB[buf][n][k0 + tig * 2];
                b[j][1] = *(const uint32_t*)&sB[buf][n][k0 + 8 + tig * 2];
            }
#pragma unroll
            for (int i = 0; i < 4; i++)
#pragma unroll
                for (int j = 0; j < 4; j++)
                    asm volatile(
                        "mma.sync.aligned.m16n8k16.row.col.f32.f16.f16.f32 "
                        "{%0,%1,%2,%3}, {%4,%5,%6,%7}, {%8,%9}, {%0,%1,%2,%3};"
                        : "+f"(acc[i][j][0]), "+f"(acc[i][j][1]),
                          "+f"(acc[i][j][2]), "+f"(acc[i][j][3])
                        : "r"(a[i][0]), "r"(a[i][1]), "r"(a[i][2]), "r"(a[i][3]),
                          "r"(b[j][0]), "r"(b[j][1]));
        }
        __syncthreads();
    }

    if (mode == 0) {
        const int gcb = g * 128 + wn * 32;
#pragma unroll
        for (int i = 0; i < 4; i++) {
            const int r = row0 + wm * 64 + i * 16 + grp;
#pragma unroll
            for (int j = 0; j < 4; j++) {
                const int col = gcb + j * 8 + tig * 2;
                *(__half2*)&g_gbuf[(size_t)r * 1664 + col] =
                    __floats2half2_rn(acc[i][j][0], acc[i][j][1]);
                *(__half2*)&g_gbuf[(size_t)(r + 8) * 1664 + col] =
                    __floats2half2_rn(acc[i][j][2], acc[i][j][3]);
            }
        }
    } else {
#pragma unroll
        for (int j = 0; j < 4; j++) {
            const int col = wn * 32 + j * 8 + tig * 2;
            const float b0 = __ldg(&bW[384 + col]);
            const float b1 = __ldg(&bW[384 + col + 1]);
#pragma unroll
            for (int i = 0; i < 4; i++) {
#pragma unroll
                for (int half = 0; half < 2; half++) {
                    const int lr = row0 + wm * 64 + i * 16 + grp + half * 8;
                    const float h0 = tanh_(acc[i][j][half * 2 + 0] + b0);
                    const float h1 = tanh_(acc[i][j][half * 2 + 1] + b1);
                    const int bb = lr >> 8, nn = lr & 255;
                    const int prow = (bb << 7) + (nn >> 1);
                    const int side = nn & 1;
                    const size_t o = (size_t)prow * 384 + 128 + side * 128 + col;
                    *(__half2*)&g_Az[1][o] = __floats2half2_rn(h0, h1);
                    *(float2*)&g_cbuf[0][(size_t)lr * 128 + col] = make_float2(0.f, 0.f);
                }
            }
        }
    }
}

// ---------------------------------------------------------------------------
// Recurrent GEMM over arity-compacted rows.
// blockIdx.x = 0..8: 0..4 = Ubin gates (bin list, K=256),
//                    5..8 = Uun gates (un list, K=128).
// Worst-case grid.y; blocks beyond the compacted count exit immediately.
// ---------------------------------------------------------------------------
__global__ __launch_bounds__(256, 2)
void gemm_rec_kernel(int azi)
{
    __shared__ __align__(16) __half sA[2][128][40];
    __shared__ __align__(16) __half sB[2][128][40];
    __shared__ int sIdx[128];

    const int gi   = (int)blockIdx.x;
    const int which = (gi < 5) ? 0 : 1;
    const int g    = (gi < 5) ? (4 + gi) : (9 + (gi - 5));
    const int nch  = (gi < 5) ? 8 : 4;          // K=256 : K=128
    const int count = g_cnt[which];
    const int row0 = (int)blockIdx.y * 128;
    if (row0 >= count) return;

    const int tid  = threadIdx.x;
    const int wid  = tid >> 5;
    const int lane = tid & 31;
    const int grp  = lane >> 2;
    const int tig  = lane & 3;
    const int wm   = wid & 1;
    const int wn   = wid >> 1;

    if (tid < 128) {
        int slot = row0 + tid;
        if (slot >= count) slot = count - 1;   // clamp: duplicate same-value writes
        sIdx[tid] = g_list[which][slot];
    }
    __syncthreads();

    const __half* A = g_Az[azi];
    const size_t gbase = (size_t)g * 32768;

    float acc[4][4][4];
#pragma unroll
    for (int i = 0; i < 4; i++)
#pragma unroll
        for (int j = 0; j < 4; j++)
#pragma unroll
            for (int q = 0; q < 4; q++) acc[i][j][q] = 0.f;

    const uint32_t sabase = (uint32_t)__cvta_generic_to_shared(&sA[0][0][0]);
    const uint32_t sbbase = (uint32_t)__cvta_generic_to_shared(&sB[0][0][0]);
    const int srow = tid >> 1;
    const int sseg = (tid & 1) * 2;
    const size_t arowoff = (size_t)sIdx[srow] * 384 + 128;   // h part of Az

    auto issue = [&](int c, int buf) {
        const __half* ap = A + arowoff + c * 32 + sseg * 8;
        const __half* bp = g_Bc + gbase + (size_t)srow * 256 + c * 32 + sseg * 8;
        const uint32_t da = sabase + (uint32_t)((buf * 128 + srow) * 80 + sseg * 16);
        const uint32_t db = sbbase + (uint32_t)((buf * 128 + srow) * 80 + sseg * 16);
        cp16(da,      ap);
        cp16(da + 16, (const char*)ap + 16);
        cp16(db,      bp);
        cp16(db + 16, (const char*)bp + 16);
        asm volatile("cp.async.commit_group;" ::: "memory");
    };

    issue(0, 0);
    for (int ci = 0; ci < nch; ci++) {
        if (ci + 1 < nch) {
            issue(ci + 1, (ci + 1) & 1);
            asm volatile("cp.async.wait_group 1;" ::: "memory");
        } else {
            asm volatile("cp.async.wait_group 0;" ::: "memory");
        }
        __syncthreads();
        const int buf = ci & 1;
#pragma unroll
        for (int ks = 0; ks < 2; ks++) {
            const int k0 = ks * 16;
            uint32_t a[4][4], b[4][2];
#pragma unroll
            for (int i = 0; i < 4; i++) {
                const int r = wm * 64 + i * 16 + grp;
                a[i][0] = *(const uint32_t*)&sA[buf][r    ][k0 + tig * 2];
                a[i][1] = *(const uint32_t*)&sA[buf][r + 8][k0 + tig * 2];
                a[i][2] = *(const uint32_t*)&sA[buf][r    ][k0 + 8 + tig * 2];
                a[i][3] = *(const uint32_t*)&sA[buf][r + 8][k0 + 8 + tig * 2];
            }
#pragma unroll
            for (int j = 0; j < 4; j++) {
                const int n = wn * 32 + j * 8 + grp;
                b[j][0] = *(const uint32_t*)&sB[buf][n][k0 + tig * 2];
                b[j][1] = *(const uint32_t*)&sB[buf][n][k0 + 8 + tig * 2];
            }
#pragma unroll
            for (int i = 0; i < 4; i++)
#pragma unroll
                for (int j = 0; j < 4; j++)
                    asm volatile(
                        "mma.sync.aligned.m16n8k16.row.col.f32.f16.f16.f32 "
                        "{%0,%1,%2,%3}, {%4,%5,%6,%7}, {%8,%9}, {%0,%1,%2,%3};"
                        : "+f"(acc[i][j][0]), "+f"(acc[i][j][1]),
                          "+f"(acc[i][j][2]), "+f"(acc[i][j][3])
                        : "r"(a[i][0]), "r"(a[i][1]), "r"(a[i][2]), "r"(a[i][3]),
                          "r"(b[j][0]), "r"(b[j][1]));
        }
        __syncthreads();
    }

    // Epilogue: scatter to gbuf at original row index
    const int gcb = g * 128 + wn * 32;
#pragma unroll
    for (int i = 0; i < 4; i++) {
        const int lr = wm * 64 + i * 16 + grp;
        const size_t r0 = (size_t)sIdx[lr]     * 1664;
        const size_t r1 = (size_t)sIdx[lr + 8] * 1664;
#pragma unroll
        for (int j = 0; j < 4; j++) {
            const int col = gcb + j * 8 + tig * 2;
            *(__half2*)&g_gbuf[r0 + col] = __floats2half2_rn(acc[i][j][0], acc[i][j][1]);
            *(__half2*)&g_gbuf[r1 + col] = __floats2half2_rn(acc[i][j][2], acc[i][j][3]);
        }
    }
}

// ---------------------------------------------------------------------------
// Pointwise LSTM cell update for level l.
// ---------------------------------------------------------------------------
__global__ __launch_bounds__(128)
void pointwise_kernel(int l, int cin,
                      const int* __restrict__ arity,
                      const float* __restrict__ bW,
                      const float* __restrict__ bUbin,
                      const float* __restrict__ bUun,
                      float* __restrict__ out)
{
    const int row = blockIdx.x;
    const int col = threadIdx.x;
    const int b = row >> l;
    const int n = row - (b << l);
    const int ar = __ldg(&arity[b * NARITY + ((1 << l) - 1) + n]);
    const size_t childrow = ((size_t)b << (l + 1)) + 2 * n;
    const float cl = g_cbuf[cin][childrow * 128 + col];
    const float cr = g_cbuf[cin][(childrow + 1) * 128 + col];
    const __half* gb = g_gbuf + (size_t)row * 1664;

    const float wx0 = __half2float(gb[0 * 128 + col]) + __ldg(&bW[0 * 128 + col]);
    const float wx1 = __half2float(gb[1 * 128 + col]) + __ldg(&bW[1 * 128 + col]);
    const float wx2 = __half2float(gb[2 * 128 + col]) + __ldg(&bW[2 * 128 + col]);
    const float wx3 = __half2float(gb[3 * 128 + col]) + __ldg(&bW[3 * 128 + col]);

    float hv, cv;
    if (ar == 1) {
        const float ig = sigmoid_(wx0 + __half2float(gb[4 * 128 + col]) + __ldg(&bUbin[0 * 128 + col]));
        const float fl = sigmoid_(wx1 + __half2float(gb[5 * 128 + col]) + __ldg(&bUbin[1 * 128 + col]));
        const float fr = sigmoid_(wx1 + __half2float(gb[6 * 128 + col]) + __ldg(&bUbin[2 * 128 + col]));
        const float og = sigmoid_(wx2 + __half2float(gb[7 * 128 + col]) + __ldg(&bUbin[3 * 128 + col]));
        const float ug = tanh_   (wx3 + __half2float(gb[8 * 128 + col]) + __ldg(&bUbin[4 * 128 + col]));
        cv = ig * ug + fl * cl + fr * cr;
        hv = og * tanh_(cv);
    } else {
        const float ig = sigmoid_(wx0 + __half2float(gb[ 9 * 128 + col]) + __ldg(&bUun[0 * 128 + col]));
        const float fg = sigmoid_(wx1 + __half2float(gb[10 * 128 + col]) + __ldg(&bUun[1 * 128 + col]));
        const float og = sigmoid_(wx2 + __half2float(gb[11 * 128 + col]) + __ldg(&bUun[2 * 128 + col]));
        const float ug = tanh_   (wx3 + __half2float(gb[12 * 128 + col]) + __ldg(&bUun[3 * 128 + col]));
        cv = ig * ug + fg * cl;
        hv = og * tanh_(cv);
    }

    g_cbuf[1 - cin][(size_t)row * 128 + col] = cv;

    if (l == 0) {
        out[row * 128 + col] = hv;
        out[BATCH * HDIM + row * 128 + col] = cv;
    } else {
        const int prow = (b << (l - 1)) + (n >> 1);
        const int side = n & 1;
        g_Az[(l - 1) & 1][(size_t)prow * 384 + 128 + side * 128 + col] =
            __float2half_rn(hv);
    }
}

// ---------------------------------------------------------------------------
extern "C" void kernel_launch(void* const* d_in, const int* in_sizes, int n_in,
                              void* d_out, int out_size)
{
    const int*   tokens = (const int*)  d_in[0];
    const int*   arity  = (const int*)  d_in[1];
    const float* emb    = (const float*)d_in[2];
    const float* W      = (const float*)d_in[3];
    const float* bW     = (const float*)d_in[4];
    const float* Ubin   = (const float*)d_in[5];
    const float* bUbin  = (const float*)d_in[6];
    const float* Uun    = (const float*)d_in[7];
    const float* bUun   = (const float*)d_in[8];
    float* out = (float*)d_out;

    prep_B_kernel<<<(13 * 128 * 256 + 255) / 256, 256>>>(W, Ubin, Uun);
    stage_leaf_kernel<<<(65536 * 128) / 256, 256>>>(tokens, emb);

    // Leaf GEMM (gate 3 = W[3])
    {
        dim3 grid(1, 65536 / 128);
        gemm_kernel<<<grid, 256>>>(1, 0, bW);
    }

    // Levels 7..0
    for (int l = 7; l >= 0; l--) {
        const int rows = BATCH << l;
        const int cin = (7 - l) & 1;
        reset_kernel<<<1, 1>>>();
        classify_kernel<<<(rows + 255) / 256, 256>>>(arity, l, rows);
        stage_x_kernel<<<(rows * 128) / 256, 256>>>(tokens, emb, l);
        // Wx gates (dense, all rows)
        {
            dim3 ggrid(4, (rows + 127) / 128);
            gemm_kernel<<<ggrid, 256>>>(0, l & 1, bW);
        }
        // Recurrent gates (compacted; early-exit beyond counts)
        {
            dim3 rgrid(9, (rows + 127) / 128);
            gemm_rec_kernel<<<rgrid, 256>>>(l & 1);
        }
        pointwise_kernel<<<rows, 128>>>(l, cin, arity, bW, bUbin, bUun,
                                        (l == 0) ? out : nullptr);
    }
}

// round 11
// speedup vs baseline: 3.8735x; 1.1716x over previous
#include <cuda_runtime.h>
#include <cuda_fp16.h>
#include <cstdint>
#include <math.h>

#define BATCH 256
#define HDIM  128
#define NTOK  511
#define NARITY 255
#define AZROWS 65280   // sum over levels 0..7 of 256*2^l

// ---------------------------------------------------------------------------
// Static device scratch:
//   Bc   : combined transposed weights [13 gates][n=128][k=256] fp16
//   Aleaf: leaf embeddings [65536][128] fp16
//   Az   : ALL levels' inputs [65280 rows][384 k] fp16, level l at row
//          off(l) = 256*(256 - 2^(l+1))  (x 0..127 | h_l 128..255 | h_r 256..383)
//   gbuf : gate pre-activations [32768][13*128] fp16 (reused per level)
//   cbuf : cell-state ping-pong [2][65536][128] fp32
//   list/cnt : per-level arity-compacted LOCAL row lists (0=binary, 1=unary)
// ---------------------------------------------------------------------------
__device__ __align__(16) __half g_Bc[13 * 128 * 256];
__device__ __align__(16) __half g_Aleaf[65536 * 128];
__device__ __align__(16) __half g_Az[AZROWS * 384];
__device__ __align__(16) __half g_gbuf[32768 * 1664];
__device__ __align__(16) float  g_cbuf[2][65536 * 128];
__device__ int g_list[8][2][32768];
__device__ int g_cnt[8][2];

__device__ __forceinline__ float sigmoid_(float x) { return 1.0f / (1.0f + expf(-x)); }
__device__ __forceinline__ float tanh_(float x)    { return 1.0f - 2.0f / (expf(2.0f * x) + 1.0f); }

__device__ __forceinline__ void cp16(uint32_t dst, const void* src) {
    asm volatile("cp.async.ca.shared.global [%0], [%1], 16;" :: "r"(dst), "l"(src));
}

// ---------------------------------------------------------------------------
// prep_B: weights -> fp16 combined-B; also zeroes the per-level counters.
// ---------------------------------------------------------------------------
__global__ void prep_B_kernel(const float* __restrict__ W,
                              const float* __restrict__ Ubin,
                              const float* __restrict__ Uun)
{
    const int idx = blockIdx.x * 256 + threadIdx.x;
    if (idx < 16) ((int*)g_cnt)[idx] = 0;
    if (idx >= 13 * 128 * 256) return;
    const int g = idx >> 15;
    const int n = (idx >> 8) & 127;
    const int k = idx & 255;
    float v;
    if (g < 4)       v = (k < 128) ? W[g * 16384 + k * 128 + n] : 0.f;
    else if (g < 9)  v = Ubin[(g - 4) * 32768 + k * 128 + n];
    else             v = (k < 128) ? Uun[(g - 9) * 16384 + k * 128 + n] : 0.f;
    g_Bc[idx] = __float2half_rn(v);
}

__global__ void stage_leaf_kernel(const int* __restrict__ tokens,
                                  const float* __restrict__ emb)
{
    const int idx = blockIdx.x * 256 + threadIdx.x;
    const int row = idx >> 7;
    const int col = idx & 127;
    const int b = row >> 8, n = row & 255;
    const int tok = __ldg(&tokens[b * NTOK + 255 + n]);
    g_Aleaf[idx] = __float2half_rn(__ldg(&emb[(size_t)tok * 128 + col]));
}

// Decode global Az row -> (level, local row). Level l occupies
// rows [off(l), off(l)+256*2^l) with off(l)=256*(256-2^(l+1)).
__device__ __forceinline__ void az_decode(int grow, int& l, int& off)
{
    const int u = AZROWS - grow;          // in (0, 65280]
    const int w = (u - 1) >> 8;
    l = 31 - __clz(w + 1);
    off = 256 * (256 - (2 << l));
}

// Stage x for ALL levels in one launch (65280 rows x 128 cols).
__global__ void stage_x_all_kernel(const int* __restrict__ tokens,
                                   const float* __restrict__ emb)
{
    const int idx = blockIdx.x * 256 + threadIdx.x;   // 0 .. 65280*128-1
    const int grow = idx >> 7;
    const int col  = idx & 127;
    int l, off;
    az_decode(grow, l, off);
    const int local = grow - off;
    const int b = local >> l;
    const int n = local - (b << l);
    const int tok = __ldg(&tokens[b * NTOK + ((1 << l) - 1) + n]);
    g_Az[(size_t)grow * 384 + col] =
        __float2half_rn(__ldg(&emb[(size_t)tok * 128 + col]));
}

// Classify ALL levels' nodes into binary/unary lists in one launch.
__global__ void classify_all_kernel(const int* __restrict__ arity)
{
    const int grow = blockIdx.x * 256 + threadIdx.x;  // 0 .. 65279
    int l, off;
    az_decode(grow, l, off);
    const int local = grow - off;
    const int b = local >> l;
    const int n = local - (b << l);
    const int ar = __ldg(&arity[b * NARITY + ((1 << l) - 1) + n]);
    const int w = (ar == 1) ? 0 : 1;
    const int pos = atomicAdd(&g_cnt[l][w], 1);
    g_list[l][w][pos] = local;
}

// ---------------------------------------------------------------------------
// Fused per-level GEMM. blockIdx.x = gate slot:
//   0..3  : Wx gates, dense over all level rows (K=128, x slots)
//   4..8  : Ubin gates over binary-compacted rows (K=256, h slots)
//   9..12 : Uun  gates over unary-compacted rows (K=128, h_l slot)
// mode 1 = leaf pass (gate 3 only, A = Aleaf, tanh epilogue into level-7 Az).
// mma.sync m16n8k16 fp16, 128x128 block tile, 8 warps 2(M)x4(N), KC=32,
// cp.async double-buffered.
// ---------------------------------------------------------------------------
__global__ __launch_bounds__(256, 2)
void gemm_kernel(int mode, int l, int off, int rows, const float* __restrict__ bW)
{
    __shared__ __align__(16) __half sA[2][128][40];
    __shared__ __align__(16) __half sB[2][128][40];
    __shared__ int sIdx[128];

    const int tid  = threadIdx.x;
    const int wid  = tid >> 5;
    const int lane = tid & 31;
    const int grp  = lane >> 2;
    const int tig  = lane & 3;
    const int wm   = wid & 1;
    const int wn   = wid >> 1;
    const int slot = (mode == 1) ? 3 : (int)blockIdx.x;
    const int row0 = (int)blockIdx.y * 128;

    int g, nch, akb, which;
    if (mode == 1 || slot < 4) { g = slot; nch = 4; akb = 0;   which = -1; }
    else if (slot < 9)         { g = slot; nch = 8; akb = 128; which = 0;  }
    else                       { g = slot; nch = 4; akb = 128; which = 1;  }

    const int srow = tid >> 1;
    const int sseg = (tid & 1) * 2;

    size_t arowoff;   // element offset of this thread's staging A-row
    if (mode == 1) {
        arowoff = (size_t)(row0 + srow) * 128;
    } else if (which < 0) {
        if (row0 >= rows) return;
        arowoff = (size_t)(off + row0 + srow) * 384;
    } else {
        const int count = g_cnt[l][which];
        if (row0 >= count) return;
        if (tid < 128) {
            int s = row0 + tid;
            if (s >= count) s = count - 1;   // clamp: duplicate writes, benign
            sIdx[tid] = g_list[l][which][s];
        }
        __syncthreads();
        arowoff = (size_t)(off + sIdx[srow]) * 384;
    }

    const __half* A = (mode == 1) ? g_Aleaf : g_Az;
    const size_t gbase = (size_t)g * 32768;

    float acc[4][4][4];
#pragma unroll
    for (int i = 0; i < 4; i++)
#pragma unroll
        for (int j = 0; j < 4; j++)
#pragma unroll
            for (int q = 0; q < 4; q++) acc[i][j][q] = 0.f;

    const uint32_t sabase = (uint32_t)__cvta_generic_to_shared(&sA[0][0][0]);
    const uint32_t sbbase = (uint32_t)__cvta_generic_to_shared(&sB[0][0][0]);

    auto issue = [&](int c, int buf) {
        const __half* ap = A + arowoff + akb + c * 32 + sseg * 8;
        const __half* bp = g_Bc + gbase + (size_t)srow * 256 + c * 32 + sseg * 8;
        const uint32_t da = sabase + (uint32_t)((buf * 128 + srow) * 80 + sseg * 16);
        const uint32_t db = sbbase + (uint32_t)((buf * 128 + srow) * 80 + sseg * 16);
        cp16(da,      ap);
        cp16(da + 16, (const char*)ap + 16);
        cp16(db,      bp);
        cp16(db + 16, (const char*)bp + 16);
        asm volatile("cp.async.commit_group;" ::: "memory");
    };

    issue(0, 0);
    for (int ci = 0; ci < nch; ci++) {
        if (ci + 1 < nch) {
            issue(ci + 1, (ci + 1) & 1);
            asm volatile("cp.async.wait_group 1;" ::: "memory");
        } else {
            asm volatile("cp.async.wait_group 0;" ::: "memory");
        }
        __syncthreads();
        const int buf = ci & 1;
#pragma unroll
        for (int ks = 0; ks < 2; ks++) {
            const int k0 = ks * 16;
            uint32_t a[4][4], b[4][2];
#pragma unroll
            for (int i = 0; i < 4; i++) {
                const int r = wm * 64 + i * 16 + grp;
                a[i][0] = *(const uint32_t*)&sA[buf][r    ][k0 + tig * 2];
                a[i][1] = *(const uint32_t*)&sA[buf][r + 8][k0 + tig * 2];
                a[i][2] = *(const uint32_t*)&sA[buf][r    ][k0 + 8 + tig * 2];
                a[i][3] = *(const uint32_t*)&sA[buf][r + 8][k0 + 8 + tig * 2];
            }
#pragma unroll
            for (int j = 0; j < 4; j++) {
                const int n = wn * 32 + j * 8 + grp;
                b[j][0] = *(const uint32_t*)&sB[buf][n][k0 + tig * 2];
                b[j][1] = *(const uint32_t*)&sB[buf][n][k0 + 8 + tig * 2];
            }
#pragma unroll
            for (int i = 0; i < 4; i++)
#pragma unroll
                for (int j = 0; j < 4; j++)
                    asm volatile(
                        "mma.sync.aligned.m16n8k16.row.col.f32.f16.f16.f32 "
                        "{%0,%1,%2,%3}, {%4,%5,%6,%7}, {%8,%9}, {%0,%1,%2,%3};"
                        : "+f"(acc[i][j][0]), "+f"(acc[i][j][1]),
                          "+f"(acc[i][j][2]), "+f"(acc[i][j][3])
                        : "r"(a[i][0]), "r"(a[i][1]), "r"(a[i][2]), "r"(a[i][3]),
                          "r"(b[j][0]), "r"(b[j][1]));
        }
        __syncthreads();
    }

    // ---- Epilogue ----
    if (mode == 0) {
        const int gcb = g * 128 + wn * 32;
#pragma unroll
        for (int i = 0; i < 4; i++) {
            const int lr = wm * 64 + i * 16 + grp;
            size_t r0, r1;
            if (which < 0) { r0 = (size_t)(row0 + lr) * 1664; r1 = (size_t)(row0 + lr + 8) * 1664; }
            else           { r0 = (size_t)sIdx[lr] * 1664;    r1 = (size_t)sIdx[lr + 8] * 1664;    }
#pragma unroll
            for (int j = 0; j < 4; j++) {
                const int col = gcb + j * 8 + tig * 2;
                *(__half2*)&g_gbuf[r0 + col] = __floats2half2_rn(acc[i][j][0], acc[i][j][1]);
                *(__half2*)&g_gbuf[r1 + col] = __floats2half2_rn(acc[i][j][2], acc[i][j][3]);
            }
        }
    } else {
        // Leaf: h = tanh(acc + bW[3]) -> level-7 Az h-slots (off(7) = 0).
#pragma unroll
        for (int j = 0; j < 4; j++) {
            const int col = wn * 32 + j * 8 + tig * 2;
            const float b0 = __ldg(&bW[384 + col]);
            const float b1 = __ldg(&bW[384 + col + 1]);
#pragma unroll
            for (int i = 0; i < 4; i++) {
#pragma unroll
                for (int half = 0; half < 2; half++) {
                    const int lr = row0 + wm * 64 + i * 16 + grp + half * 8;
                    const float h0 = tanh_(acc[i][j][half * 2 + 0] + b0);
                    const float h1 = tanh_(acc[i][j][half * 2 + 1] + b1);
                    const int bb = lr >> 8, nn = lr & 255;
                    const int prow = (bb << 7) + (nn >> 1);
                    const int side = nn & 1;
                    const size_t o = (size_t)prow * 384 + 128 + side * 128 + col;
                    *(__half2*)&g_Az[o] = __floats2half2_rn(h0, h1);
                }
            }
        }
    }
}

// ---------------------------------------------------------------------------
// Pointwise LSTM cell update for level l. czero: children are leaves (c = 0).
// ---------------------------------------------------------------------------
__global__ __launch_bounds__(128)
void pointwise_kernel(int l, int cin, int czero, int poff,
                      const int* __restrict__ arity,
                      const float* __restrict__ bW,
                      const float* __restrict__ bUbin,
                      const float* __restrict__ bUun,
                      float* __restrict__ out)
{
    const int row = blockIdx.x;
    const int col = threadIdx.x;
    const int b = row >> l;
    const int n = row - (b << l);
    const int ar = __ldg(&arity[b * NARITY + ((1 << l) - 1) + n]);
    const size_t childrow = ((size_t)b << (l + 1)) + 2 * n;
    const float cl = czero ? 0.f : g_cbuf[cin][childrow * 128 + col];
    const float cr = czero ? 0.f : g_cbuf[cin][(childrow + 1) * 128 + col];
    const __half* gb = g_gbuf + (size_t)row * 1664;

    const float wx0 = __half2float(gb[0 * 128 + col]) + __ldg(&bW[0 * 128 + col]);
    const float wx1 = __half2float(gb[1 * 128 + col]) + __ldg(&bW[1 * 128 + col]);
    const float wx2 = __half2float(gb[2 * 128 + col]) + __ldg(&bW[2 * 128 + col]);
    const float wx3 = __half2float(gb[3 * 128 + col]) + __ldg(&bW[3 * 128 + col]);

    float hv, cv;
    if (ar == 1) {
        const float ig = sigmoid_(wx0 + __half2float(gb[4 * 128 + col]) + __ldg(&bUbin[0 * 128 + col]));
        const float fl = sigmoid_(wx1 + __half2float(gb[5 * 128 + col]) + __ldg(&bUbin[1 * 128 + col]));
        const float fr = sigmoid_(wx1 + __half2float(gb[6 * 128 + col]) + __ldg(&bUbin[2 * 128 + col]));
        const float og = sigmoid_(wx2 + __half2float(gb[7 * 128 + col]) + __ldg(&bUbin[3 * 128 + col]));
        const float ug = tanh_   (wx3 + __half2float(gb[8 * 128 + col]) + __ldg(&bUbin[4 * 128 + col]));
        cv = ig * ug + fl * cl + fr * cr;
        hv = og * tanh_(cv);
    } else {
        const float ig = sigmoid_(wx0 + __half2float(gb[ 9 * 128 + col]) + __ldg(&bUun[0 * 128 + col]));
        const float fg = sigmoid_(wx1 + __half2float(gb[10 * 128 + col]) + __ldg(&bUun[1 * 128 + col]));
        const float og = sigmoid_(wx2 + __half2float(gb[11 * 128 + col]) + __ldg(&bUun[2 * 128 + col]));
        const float ug = tanh_   (wx3 + __half2float(gb[12 * 128 + col]) + __ldg(&bUun[3 * 128 + col]));
        cv = ig * ug + fg * cl;
        hv = og * tanh_(cv);
    }

    g_cbuf[1 - cin][(size_t)row * 128 + col] = cv;

    if (l == 0) {
        out[row * 128 + col] = hv;
        out[BATCH * HDIM + row * 128 + col] = cv;
    } else {
        const int prow = (b << (l - 1)) + (n >> 1);
        const int side = n & 1;
        g_Az[(size_t)(poff + prow) * 384 + 128 + side * 128 + col] =
            __float2half_rn(hv);
    }
}

// ---------------------------------------------------------------------------
extern "C" void kernel_launch(void* const* d_in, const int* in_sizes, int n_in,
                              void* d_out, int out_size)
{
    const int*   tokens = (const int*)  d_in[0];
    const int*   arity  = (const int*)  d_in[1];
    const float* emb    = (const float*)d_in[2];
    const float* W      = (const float*)d_in[3];
    const float* bW     = (const float*)d_in[4];
    const float* Ubin   = (const float*)d_in[5];
    const float* bUbin  = (const float*)d_in[6];
    const float* Uun    = (const float*)d_in[7];
    const float* bUun   = (const float*)d_in[8];
    float* out = (float*)d_out;

    prep_B_kernel<<<(13 * 128 * 256 + 255) / 256, 256>>>(W, Ubin, Uun);
    stage_leaf_kernel<<<(65536 * 128) / 256, 256>>>(tokens, emb);
    stage_x_all_kernel<<<(AZROWS * 128) / 256, 256>>>(tokens, emb);
    classify_all_kernel<<<AZROWS / 256, 256>>>(arity);

    // Leaf GEMM (gate 3 = W[3]) -> level-7 Az h-slots
    {
        dim3 grid(1, 65536 / 128);
        gemm_kernel<<<grid, 256>>>(1, 7, 0, 65536, bW);
    }

    // Levels 7..0: one fused GEMM + one pointwise per level
    for (int l = 7; l >= 0; l--) {
        const int rows = BATCH << l;
        const int off  = 256 * (256 - (2 << l));
        const int poff = (l > 0) ? 256 * (256 - (1 << l)) : 0;
        const int cin  = (7 - l) & 1;
        dim3 ggrid(13, rows / 128);
        gemm_kernel<<<ggrid, 256>>>(0, l, off, rows, bW);
        pointwise_kernel<<<rows, 128>>>(l, cin, (l == 7) ? 1 : 0, poff,
                                        arity, bW, bUbin, bUun,
                                        (l == 0) ? out : nullptr);
    }
}